// round 1
// baseline (speedup 1.0000x reference)
#include <cuda_runtime.h>
#include <math.h>

#define B_ 2
#define L_ 2048
#define D_ 1024
#define H_ 16
#define DH_ 64
#define FF_ 4096
#define EPS_ 1e-5f

// ---------------- scratch buffers (device globals; no allocation allowed) ----------------
__device__ float g_h[B_ * L_ * D_];        // ln1 out, later ln2 out (reused)
__device__ float g_q[B_ * L_ * D_];
__device__ float g_k[B_ * L_ * D_];
__device__ float g_v[B_ * L_ * D_];
__device__ float g_ao[B_ * L_ * D_];       // attention output (B,L,D) with head-concat layout
__device__ float g_x2[B_ * L_ * D_];       // residual after attention
__device__ float g_ff[B_ * L_ * FF_];      // MLP hidden

// ---------------- LayerNorm (+ optional pos embed add) ----------------
// one block per row; 256 threads; D=1024 => one float4 per thread
__global__ void ln_kernel(const float* __restrict__ x,
                          const float* __restrict__ gamma,
                          const float* __restrict__ beta,
                          const float* __restrict__ pos,   // may be null
                          float* __restrict__ out) {
    int row = blockIdx.x;                // 0..B*L-1
    int l = row & (L_ - 1);
    const float* xr = x + (size_t)row * D_;
    int t = threadIdx.x;                 // 0..255
    float4 v = *(const float4*)(xr + t * 4);

    float s  = v.x + v.y + v.z + v.w;
    float sq = v.x * v.x + v.y * v.y + v.z * v.z + v.w * v.w;
    #pragma unroll
    for (int o = 16; o > 0; o >>= 1) {
        s  += __shfl_down_sync(0xffffffffu, s,  o);
        sq += __shfl_down_sync(0xffffffffu, sq, o);
    }
    __shared__ float ss[8], sqs[8], stats[2];
    int wid = t >> 5, lane = t & 31;
    if (lane == 0) { ss[wid] = s; sqs[wid] = sq; }
    __syncthreads();
    if (t == 0) {
        float S = 0.f, SQ = 0.f;
        #pragma unroll
        for (int i = 0; i < 8; i++) { S += ss[i]; SQ += sqs[i]; }
        float mu = S / (float)D_;
        float var = SQ / (float)D_ - mu * mu;
        stats[0] = mu;
        stats[1] = rsqrtf(var + EPS_);
    }
    __syncthreads();
    float mu = stats[0], rs = stats[1];

    float4 g4 = *(const float4*)(gamma + t * 4);
    float4 b4 = *(const float4*)(beta + t * 4);
    float4 r;
    r.x = (v.x - mu) * rs * g4.x + b4.x;
    r.y = (v.y - mu) * rs * g4.y + b4.y;
    r.z = (v.z - mu) * rs * g4.z + b4.z;
    r.w = (v.w - mu) * rs * g4.w + b4.w;
    if (pos) {
        float4 p4 = *(const float4*)(pos + (size_t)l * D_ + t * 4);
        r.x += p4.x; r.y += p4.y; r.z += p4.z; r.w += p4.w;
    }
    *(float4*)(out + (size_t)row * D_ + t * 4) = r;
}

// ---------------- SGEMM: C[M,N] = A[M,K] @ W[K,N] (+bias)(+gelu)(+addsrc) ----------------
// 128x128 block tile, BK=16, 256 threads, 8x8 per thread.
__global__ __launch_bounds__(256, 2)
void sgemm128(const float* __restrict__ A,
              const float* __restrict__ W,
              const float* __restrict__ bias,    // may be null, length N
              const float* __restrict__ addsrc,  // may be null, same shape as C
              float* __restrict__ C,
              int M, int N, int K, int gelu_flag) {
    __shared__ float As[16][132];
    __shared__ float Bs[16][132];

    int t = threadIdx.x;
    int tx = t & 15, ty = t >> 4;
    int n0 = blockIdx.x * 128;
    int m0 = blockIdx.y * 128;

    float acc[8][8];
    #pragma unroll
    for (int i = 0; i < 8; i++)
        #pragma unroll
        for (int j = 0; j < 8; j++) acc[i][j] = 0.f;

    int arow = t >> 2;            // 0..63
    int acol = (t & 3) * 4;       // 0,4,8,12
    int brow = t >> 4;            // 0..15
    int bcol = (t & 15) * 4;      // 0..60

    for (int k0 = 0; k0 < K; k0 += 16) {
        #pragma unroll
        for (int hh = 0; hh < 2; hh++) {
            float4 va = *(const float4*)(A + (size_t)(m0 + arow + 64 * hh) * K + k0 + acol);
            As[acol + 0][arow + 64 * hh] = va.x;
            As[acol + 1][arow + 64 * hh] = va.y;
            As[acol + 2][arow + 64 * hh] = va.z;
            As[acol + 3][arow + 64 * hh] = va.w;
        }
        #pragma unroll
        for (int hh = 0; hh < 2; hh++) {
            float4 vb = *(const float4*)(W + (size_t)(k0 + brow) * N + n0 + bcol + 64 * hh);
            *(float4*)&Bs[brow][bcol + 64 * hh] = vb;
        }
        __syncthreads();

        #pragma unroll
        for (int kk = 0; kk < 16; kk++) {
            float a[8], b[8];
            *(float4*)(a)     = *(float4*)&As[kk][ty * 8];
            *(float4*)(a + 4) = *(float4*)&As[kk][ty * 8 + 4];
            *(float4*)(b)     = *(float4*)&Bs[kk][tx * 8];
            *(float4*)(b + 4) = *(float4*)&Bs[kk][tx * 8 + 4];
            #pragma unroll
            for (int i = 0; i < 8; i++)
                #pragma unroll
                for (int j = 0; j < 8; j++)
                    acc[i][j] += a[i] * b[j];
        }
        __syncthreads();
    }

    // epilogue
    int row0 = m0 + ty * 8;
    int col0 = n0 + tx * 8;
    float bi[8];
    #pragma unroll
    for (int j = 0; j < 8; j++) bi[j] = bias ? bias[col0 + j] : 0.f;

    #pragma unroll
    for (int i = 0; i < 8; i++) {
        size_t roff = (size_t)(row0 + i) * N + col0;
        #pragma unroll
        for (int jj = 0; jj < 8; jj += 4) {
            float val[4];
            #pragma unroll
            for (int u = 0; u < 4; u++) {
                float vv = acc[i][jj + u] + bi[jj + u];
                if (gelu_flag) vv = 0.5f * vv * (1.f + erff(vv * 0.70710678118654752f));
                val[u] = vv;
            }
            if (addsrc) {
                float4 srcv = *(const float4*)(addsrc + roff + jj);
                val[0] += srcv.x; val[1] += srcv.y; val[2] += srcv.z; val[3] += srcv.w;
            }
            float4 wv = make_float4(val[0], val[1], val[2], val[3]);
            *(float4*)(C + roff + jj) = wv;
        }
    }
}

// ---------------- fused attention (flash-style, fp32) ----------------
// grid: (L/64, B*H), 256 threads. BQ=BK=64, DH=64. dynamic smem.
#define ASTR 68
__global__ void attn_kernel(const float* __restrict__ q,
                            const float* __restrict__ k,
                            const float* __restrict__ v,
                            float* __restrict__ o) {
    int bh = blockIdx.y;
    int b = bh / H_;
    int h = bh % H_;
    int q0 = blockIdx.x * 64;

    extern __shared__ float sm[];
    float* Qs  = sm;                   // [64][ASTR]  Q row-major (scaled)
    float* KPs = Qs + 64 * ASTR;       // K^T [d][kidx] then P [q][kidx]
    float* Vs  = KPs + 64 * ASTR;      // V row-major [kidx][d]
    float* red = Vs + 64 * ASTR;       // [64][16]
    float* m_s = red + 64 * 16;
    float* l_s = m_s + 64;
    float* a_s = l_s + 64;

    int t = threadIdx.x;
    int tx = t & 15, ty = t >> 4;
    const float scale = 0.125f;        // DH^-0.5
    size_t base = ((size_t)b * L_) * D_ + (size_t)h * DH_;

    // load Q tile (pre-scaled)
    for (int i = t; i < 64 * 16; i += 256) {
        int r = i >> 4, cg = (i & 15) * 4;
        float4 vq = *(const float4*)(q + base + (size_t)(q0 + r) * D_ + cg);
        Qs[r * ASTR + cg + 0] = vq.x * scale;
        Qs[r * ASTR + cg + 1] = vq.y * scale;
        Qs[r * ASTR + cg + 2] = vq.z * scale;
        Qs[r * ASTR + cg + 3] = vq.w * scale;
    }
    if (t < 64) { m_s[t] = -INFINITY; l_s[t] = 0.f; }

    float acc[4][4];
    #pragma unroll
    for (int i = 0; i < 4; i++)
        #pragma unroll
        for (int j = 0; j < 4; j++) acc[i][j] = 0.f;

    __syncthreads();

    for (int k0 = 0; k0 < L_; k0 += 64) {
        // load K (transposed into smem) and V (row-major)
        for (int i = t; i < 64 * 16; i += 256) {
            int r = i >> 4, cg = (i & 15) * 4;
            float4 vk = *(const float4*)(k + base + (size_t)(k0 + r) * D_ + cg);
            KPs[(cg + 0) * ASTR + r] = vk.x;
            KPs[(cg + 1) * ASTR + r] = vk.y;
            KPs[(cg + 2) * ASTR + r] = vk.z;
            KPs[(cg + 3) * ASTR + r] = vk.w;
            float4 vv = *(const float4*)(v + base + (size_t)(k0 + r) * D_ + cg);
            *(float4*)&Vs[r * ASTR + cg] = vv;
        }
        __syncthreads();

        // S = Q K^T (4x4 per thread)
        float s[4][4];
        #pragma unroll
        for (int i = 0; i < 4; i++)
            #pragma unroll
            for (int j = 0; j < 4; j++) s[i][j] = 0.f;
        #pragma unroll 4
        for (int d = 0; d < 64; d++) {
            float4 bk = *(float4*)&KPs[d * ASTR + tx * 4];
            float a0 = Qs[(ty * 4 + 0) * ASTR + d];
            float a1 = Qs[(ty * 4 + 1) * ASTR + d];
            float a2 = Qs[(ty * 4 + 2) * ASTR + d];
            float a3 = Qs[(ty * 4 + 3) * ASTR + d];
            s[0][0] += a0 * bk.x; s[0][1] += a0 * bk.y; s[0][2] += a0 * bk.z; s[0][3] += a0 * bk.w;
            s[1][0] += a1 * bk.x; s[1][1] += a1 * bk.y; s[1][2] += a1 * bk.z; s[1][3] += a1 * bk.w;
            s[2][0] += a2 * bk.x; s[2][1] += a2 * bk.y; s[2][2] += a2 * bk.z; s[2][3] += a2 * bk.w;
            s[3][0] += a3 * bk.x; s[3][1] += a3 * bk.y; s[3][2] += a3 * bk.z; s[3][3] += a3 * bk.w;
        }
        // partial row maxes
        #pragma unroll
        for (int i = 0; i < 4; i++) {
            float mx = fmaxf(fmaxf(s[i][0], s[i][1]), fmaxf(s[i][2], s[i][3]));
            red[(ty * 4 + i) * 16 + tx] = mx;
        }
        __syncthreads();           // all S done (K^T no longer needed), red ready
        if (t < 64) {
            float mt = red[t * 16];
            #pragma unroll
            for (int j = 1; j < 16; j++) mt = fmaxf(mt, red[t * 16 + j]);
            float mo = m_s[t];
            float mn = fmaxf(mo, mt);
            a_s[t] = expf(mo - mn);
            m_s[t] = mn;
        }
        __syncthreads();
        // P = exp(S - m); write into KPs (overwriting K^T); partial row sums
        #pragma unroll
        for (int i = 0; i < 4; i++) {
            float mrow = m_s[ty * 4 + i];
            float p0 = expf(s[i][0] - mrow);
            float p1 = expf(s[i][1] - mrow);
            float p2 = expf(s[i][2] - mrow);
            float p3 = expf(s[i][3] - mrow);
            *(float4*)&KPs[(ty * 4 + i) * ASTR + tx * 4] = make_float4(p0, p1, p2, p3);
            red[(ty * 4 + i) * 16 + tx] = p0 + p1 + p2 + p3;
        }
        __syncthreads();
        if (t < 64) {
            float sum = 0.f;
            #pragma unroll
            for (int j = 0; j < 16; j++) sum += red[t * 16 + j];
            l_s[t] = l_s[t] * a_s[t] + sum;
        }
        // O = O*alpha + P @ V
        float al[4];
        #pragma unroll
        for (int i = 0; i < 4; i++) al[i] = a_s[ty * 4 + i];
        #pragma unroll
        for (int i = 0; i < 4; i++)
            #pragma unroll
            for (int j = 0; j < 4; j++) acc[i][j] *= al[i];
        #pragma unroll 4
        for (int kk = 0; kk < 64; kk++) {
            float4 bv = *(float4*)&Vs[kk * ASTR + tx * 4];
            float p0 = KPs[(ty * 4 + 0) * ASTR + kk];
            float p1 = KPs[(ty * 4 + 1) * ASTR + kk];
            float p2 = KPs[(ty * 4 + 2) * ASTR + kk];
            float p3 = KPs[(ty * 4 + 3) * ASTR + kk];
            acc[0][0] += p0 * bv.x; acc[0][1] += p0 * bv.y; acc[0][2] += p0 * bv.z; acc[0][3] += p0 * bv.w;
            acc[1][0] += p1 * bv.x; acc[1][1] += p1 * bv.y; acc[1][2] += p1 * bv.z; acc[1][3] += p1 * bv.w;
            acc[2][0] += p2 * bv.x; acc[2][1] += p2 * bv.y; acc[2][2] += p2 * bv.z; acc[2][3] += p2 * bv.w;
            acc[3][0] += p3 * bv.x; acc[3][1] += p3 * bv.y; acc[3][2] += p3 * bv.z; acc[3][3] += p3 * bv.w;
        }
        __syncthreads();           // before overwriting KPs/Vs next tile
    }

    // finalize: divide by l, write out [b, q0+row, h*DH + col]
    #pragma unroll
    for (int i = 0; i < 4; i++) {
        float inv = 1.f / l_s[ty * 4 + i];
        float4 wv = make_float4(acc[i][0] * inv, acc[i][1] * inv, acc[i][2] * inv, acc[i][3] * inv);
        *(float4*)(o + base + (size_t)(q0 + ty * 4 + i) * D_ + tx * 4) = wv;
    }
}

// ---------------- launch ----------------
extern "C" void kernel_launch(void* const* d_in, const int* in_sizes, int n_in,
                              void* d_out, int out_size) {
    const float* x     = (const float*)d_in[0];
    const float* pos   = (const float*)d_in[1];
    const float* ln1_g = (const float*)d_in[2];
    const float* ln1_b = (const float*)d_in[3];
    const float* Wq    = (const float*)d_in[4];
    const float* Wk    = (const float*)d_in[5];
    const float* Wv    = (const float*)d_in[6];
    const float* Wo    = (const float*)d_in[7];
    const float* bo    = (const float*)d_in[8];
    const float* ln2_g = (const float*)d_in[9];
    const float* ln2_b = (const float*)d_in[10];
    const float* W1    = (const float*)d_in[11];
    const float* b1    = (const float*)d_in[12];
    const float* W2    = (const float*)d_in[13];
    const float* b2    = (const float*)d_in[14];
    float* out = (float*)d_out;

    float *h, *q, *k, *v, *ao, *x2, *ff;
    cudaGetSymbolAddress((void**)&h,  g_h);
    cudaGetSymbolAddress((void**)&q,  g_q);
    cudaGetSymbolAddress((void**)&k,  g_k);
    cudaGetSymbolAddress((void**)&v,  g_v);
    cudaGetSymbolAddress((void**)&ao, g_ao);
    cudaGetSymbolAddress((void**)&x2, g_x2);
    cudaGetSymbolAddress((void**)&ff, g_ff);

    const int ROWS = B_ * L_;   // 4096

    // 1) h = LN1(x) + pos
    ln_kernel<<<ROWS, 256>>>(x, ln1_g, ln1_b, pos, h);

    // 2-4) q/k/v projections
    {
        dim3 grid(D_ / 128, ROWS / 128);
        sgemm128<<<grid, 256>>>(h, Wq, nullptr, nullptr, q, ROWS, D_, D_, 0);
        sgemm128<<<grid, 256>>>(h, Wk, nullptr, nullptr, k, ROWS, D_, D_, 0);
        sgemm128<<<grid, 256>>>(h, Wv, nullptr, nullptr, v, ROWS, D_, D_, 0);
    }

    // 5) fused attention
    {
        int smem = (3 * 64 * ASTR + 64 * 16 + 3 * 64) * (int)sizeof(float);  // 57088
        cudaFuncSetAttribute(attn_kernel, cudaFuncAttributeMaxDynamicSharedMemorySize, smem);
        dim3 grid(L_ / 64, B_ * H_);
        attn_kernel<<<grid, 256, smem>>>(q, k, v, ao);
    }

    // 6) x2 = x + ao @ Wo + bo
    {
        dim3 grid(D_ / 128, ROWS / 128);
        sgemm128<<<grid, 256>>>(ao, Wo, bo, x, x2, ROWS, D_, D_, 0);
    }

    // 7) m = LN2(x2)  (reuse h)
    ln_kernel<<<ROWS, 256>>>(x2, ln2_g, ln2_b, nullptr, h);

    // 8) ff = gelu(m @ W1 + b1)
    {
        dim3 grid(FF_ / 128, ROWS / 128);
        sgemm128<<<grid, 256>>>(h, W1, b1, nullptr, ff, ROWS, FF_, D_, 1);
    }

    // 9) out = x2 + ff @ W2 + b2
    {
        dim3 grid(D_ / 128, ROWS / 128);
        sgemm128<<<grid, 256>>>(ff, W2, b2, x2, out, ROWS, D_, FF_, 0);
    }
}

// round 4
// speedup vs baseline: 1.6405x; 1.6405x over previous
#include <cuda_runtime.h>
#include <math.h>
#include <stdint.h>

#define B_ 2
#define L_ 2048
#define D_ 1024
#define H_ 16
#define DH_ 64
#define FF_ 4096
#define EPS_ 1e-5f

// ---------------- scratch (device globals) ----------------
__device__ float g_h[B_ * L_ * D_];
__device__ float g_q[B_ * L_ * D_];
__device__ float g_k[B_ * L_ * D_];
__device__ float g_v[B_ * L_ * D_];
__device__ float g_ao[B_ * L_ * D_];
__device__ float g_x2[B_ * L_ * D_];
__device__ float g_ff[B_ * L_ * FF_];
__device__ float g_wqT[D_ * D_];
__device__ float g_wkT[D_ * D_];
__device__ float g_wvT[D_ * D_];
__device__ float g_woT[D_ * D_];
__device__ float g_w1T[FF_ * D_];   // [FF][D] K-major
__device__ float g_w2T[D_ * FF_];   // [D][FF] K-major

// ---------------- helpers ----------------
__device__ __forceinline__ uint32_t smem_u32(const void* p) {
    uint32_t a;
    asm("{ .reg .u64 t; cvta.to.shared.u64 t, %1; cvt.u32.u64 %0, t; }" : "=r"(a) : "l"(p));
    return a;
}
__device__ __forceinline__ float rtf32(float x) {
    uint32_t u;
    asm("cvt.rna.tf32.f32 %0, %1;" : "=r"(u) : "f"(x));
    return __uint_as_float(u);
}
__device__ __forceinline__ void mma_tf32(float* c, const uint32_t* a, const uint32_t* b) {
    asm volatile(
        "mma.sync.aligned.m16n8k8.row.col.f32.tf32.tf32.f32 "
        "{%0,%1,%2,%3}, {%4,%5,%6,%7}, {%8,%9}, {%0,%1,%2,%3};"
        : "+f"(c[0]), "+f"(c[1]), "+f"(c[2]), "+f"(c[3])
        : "r"(a[0]), "r"(a[1]), "r"(a[2]), "r"(a[3]), "r"(b[0]), "r"(b[1]));
}

#define CP_ASYNC16(dst, src) \
    asm volatile("cp.async.cg.shared.global [%0], [%1], 16;" :: "r"(dst), "l"(src))
#define CP_COMMIT() asm volatile("cp.async.commit_group;" ::: "memory")
#define CP_WAIT(n)  asm volatile("cp.async.wait_group %0;" :: "n"(n) : "memory")

// ---------------- LayerNorm (+pos), output rounded to tf32 ----------------
__global__ void ln_kernel(const float* __restrict__ x,
                          const float* __restrict__ gamma,
                          const float* __restrict__ beta,
                          const float* __restrict__ pos,
                          float* __restrict__ out) {
    int row = blockIdx.x;
    int l = row & (L_ - 1);
    const float* xr = x + (size_t)row * D_;
    int t = threadIdx.x;
    float4 v = *(const float4*)(xr + t * 4);

    float s = v.x + v.y + v.z + v.w;
    float sq = v.x * v.x + v.y * v.y + v.z * v.z + v.w * v.w;
    #pragma unroll
    for (int o = 16; o > 0; o >>= 1) {
        s  += __shfl_down_sync(0xffffffffu, s,  o);
        sq += __shfl_down_sync(0xffffffffu, sq, o);
    }
    __shared__ float ss[8], sqs[8], stats[2];
    int wid = t >> 5, lane = t & 31;
    if (lane == 0) { ss[wid] = s; sqs[wid] = sq; }
    __syncthreads();
    if (t == 0) {
        float S = 0.f, SQ = 0.f;
        #pragma unroll
        for (int i = 0; i < 8; i++) { S += ss[i]; SQ += sqs[i]; }
        float mu = S / (float)D_;
        float var = SQ / (float)D_ - mu * mu;
        stats[0] = mu;
        stats[1] = rsqrtf(var + EPS_);
    }
    __syncthreads();
    float mu = stats[0], rs = stats[1];

    float4 g4 = *(const float4*)(gamma + t * 4);
    float4 b4 = *(const float4*)(beta + t * 4);
    float4 r;
    r.x = (v.x - mu) * rs * g4.x + b4.x;
    r.y = (v.y - mu) * rs * g4.y + b4.y;
    r.z = (v.z - mu) * rs * g4.z + b4.z;
    r.w = (v.w - mu) * rs * g4.w + b4.w;
    if (pos) {
        float4 p4 = *(const float4*)(pos + (size_t)l * D_ + t * 4);
        r.x += p4.x; r.y += p4.y; r.z += p4.z; r.w += p4.w;
    }
    r.x = rtf32(r.x); r.y = rtf32(r.y); r.z = rtf32(r.z); r.w = rtf32(r.w);
    *(float4*)(out + (size_t)row * D_ + t * 4) = r;
}

// ---------------- weight transpose + tf32 round: WT[n][k] = rtf32(W[k][n]) ----------------
__global__ void transpose_tf32(const float* __restrict__ W, float* __restrict__ WT, int K, int N) {
    __shared__ float tile[32][33];
    int n0 = blockIdx.x * 32, k0 = blockIdx.y * 32;
    int tx = threadIdx.x, ty = threadIdx.y;
    #pragma unroll
    for (int i = 0; i < 4; i++)
        tile[ty + 8 * i][tx] = W[(size_t)(k0 + ty + 8 * i) * N + n0 + tx];
    __syncthreads();
    #pragma unroll
    for (int i = 0; i < 4; i++)
        WT[(size_t)(n0 + ty + 8 * i) * K + k0 + tx] = rtf32(tile[tx][ty + 8 * i]);
}

// ---------------- tf32 mma.sync GEMM ----------------
// C[M,N] = A[M,K] @ BT[N,K]^T, both K-major, tf32-prerounded.
// 128x128 tile, BK=32, 8 warps (2m x 4n), warp tile 64x32, m16n8k8 frags.
// flags: bit0 = gelu, bit1 = round output to tf32
#define AST 36
#define GEMM_SMEM_FLOATS (4 * 128 * AST + 128)
#define GEMM_SMEM_BYTES  (GEMM_SMEM_FLOATS * 4)

__global__ __launch_bounds__(256, 2)
void gemm_mma(const float* __restrict__ A, const float* __restrict__ BT,
              const float* __restrict__ bias, const float* __restrict__ addsrc,
              float* __restrict__ C, int M, int N, int K, int flags) {
    extern __shared__ float sm[];
    float* As0 = sm;
    float* Bs0 = sm + 128 * AST;
    float* As1 = sm + 2 * 128 * AST;
    float* Bs1 = sm + 3 * 128 * AST;
    float* bias_s = sm + 4 * 128 * AST;

    int t = threadIdx.x;
    int wid = t >> 5, lane = t & 31;
    int wm = wid & 1, wn = wid >> 1;
    int gid = lane >> 2, tig = lane & 3;
    int n0 = blockIdx.x * 128, m0 = blockIdx.y * 128;

    uint32_t sA[2] = { smem_u32(As0), smem_u32(As1) };
    uint32_t sB[2] = { smem_u32(Bs0), smem_u32(Bs1) };

    if (t < 32) {
        float4 bv = bias ? *(const float4*)(bias + n0 + t * 4) : make_float4(0.f, 0.f, 0.f, 0.f);
        *(float4*)(bias_s + t * 4) = bv;
    }

    // loader: tile is 128 rows x 32 cols (K-major), 8 float4/row.
    // 2 threads per row; each thread loads 4 contiguous float4 (64B).
    int lrow = t >> 1;                 // 0..127
    int lc4  = (t & 1) * 4;            // float4 base index: 0 or 4
    #define LOAD_TILE(buf, kk0) do { \
        _Pragma("unroll") \
        for (int j = 0; j < 4; j++) { \
            uint32_t off = (uint32_t)(lrow * AST + (lc4 + j) * 4) * 4u; \
            CP_ASYNC16(sA[buf] + off, A + (size_t)(m0 + lrow) * K + (kk0) + (lc4 + j) * 4); \
            CP_ASYNC16(sB[buf] + off, BT + (size_t)(n0 + lrow) * K + (kk0) + (lc4 + j) * 4); \
        } \
    } while (0)

    float acc[4][4][4];
    #pragma unroll
    for (int i = 0; i < 4; i++)
        #pragma unroll
        for (int j = 0; j < 4; j++)
            #pragma unroll
            for (int c = 0; c < 4; c++) acc[i][j][c] = 0.f;

    const int NS = K >> 5;
    LOAD_TILE(0, 0);
    CP_COMMIT();

    for (int s = 0; s < NS; s++) {
        if (s + 1 < NS) {
            LOAD_TILE((s + 1) & 1, (s + 1) << 5);
            CP_COMMIT();
            CP_WAIT(1);
        } else {
            CP_WAIT(0);
        }
        __syncthreads();

        const float* as = (s & 1) ? As1 : As0;
        const float* bs = (s & 1) ? Bs1 : Bs0;
        int arow = wm * 64 + gid;
        int bcol = wn * 32 + gid;

        #pragma unroll
        for (int kk = 0; kk < 4; kk++) {
            int kb = kk * 8 + tig;
            uint32_t af[4][4];
            #pragma unroll
            for (int mf = 0; mf < 4; mf++) {
                int r = arow + mf * 16;
                af[mf][0] = __float_as_uint(as[r * AST + kb]);
                af[mf][1] = __float_as_uint(as[(r + 8) * AST + kb]);
                af[mf][2] = __float_as_uint(as[r * AST + kb + 4]);
                af[mf][3] = __float_as_uint(as[(r + 8) * AST + kb + 4]);
            }
            uint32_t bf[4][2];
            #pragma unroll
            for (int nf = 0; nf < 4; nf++) {
                int c = bcol + nf * 8;
                bf[nf][0] = __float_as_uint(bs[c * AST + kb]);
                bf[nf][1] = __float_as_uint(bs[c * AST + kb + 4]);
            }
            #pragma unroll
            for (int mf = 0; mf < 4; mf++)
                #pragma unroll
                for (int nf = 0; nf < 4; nf++)
                    mma_tf32(acc[mf][nf], af[mf], bf[nf]);
        }
        __syncthreads();
    }

    // epilogue
    bool do_gelu = (flags & 1), do_round = (flags & 2);
    int row_base = m0 + wm * 64 + gid;
    int colw = wn * 32;                     // warp col offset within 128 tile
    #pragma unroll
    for (int mf = 0; mf < 4; mf++) {
        #pragma unroll
        for (int rr = 0; rr < 2; rr++) {
            int grow = row_base + mf * 16 + rr * 8;
            size_t roff = (size_t)grow * N + n0 + colw;
            #pragma unroll
            for (int nf = 0; nf < 4; nf++) {
                int cl = colw + nf * 8 + tig * 2;   // within 128 tile
                float v0 = acc[mf][nf][rr * 2 + 0] + bias_s[cl];
                float v1 = acc[mf][nf][rr * 2 + 1] + bias_s[cl + 1];
                if (do_gelu) {
                    v0 = 0.5f * v0 * (1.f + erff(v0 * 0.70710678118654752f));
                    v1 = 0.5f * v1 * (1.f + erff(v1 * 0.70710678118654752f));
                }
                if (addsrc) {
                    float2 sv = *(const float2*)(addsrc + roff + nf * 8 + tig * 2);
                    v0 += sv.x; v1 += sv.y;
                }
                if (do_round) { v0 = rtf32(v0); v1 = rtf32(v1); }
                *(float2*)(C + roff + nf * 8 + tig * 2) = make_float2(v0, v1);
            }
        }
    }
    #undef LOAD_TILE
}

// ---------------- fused attention (fp32 flash, output tf32-rounded) ----------------
#define ASTR 68
__global__ void attn_kernel(const float* __restrict__ q,
                            const float* __restrict__ k,
                            const float* __restrict__ v,
                            float* __restrict__ o) {
    int bh = blockIdx.y;
    int b = bh / H_;
    int h = bh % H_;
    int q0 = blockIdx.x * 64;

    extern __shared__ float sm[];
    float* Qs  = sm;
    float* KPs = Qs + 64 * ASTR;
    float* Vs  = KPs + 64 * ASTR;
    float* red = Vs + 64 * ASTR;
    float* m_s = red + 64 * 16;
    float* l_s = m_s + 64;
    float* a_s = l_s + 64;

    int t = threadIdx.x;
    int tx = t & 15, ty = t >> 4;
    const float scale = 0.125f;
    size_t base = ((size_t)b * L_) * D_ + (size_t)h * DH_;

    for (int i = t; i < 64 * 16; i += 256) {
        int r = i >> 4, cg = (i & 15) * 4;
        float4 vq = *(const float4*)(q + base + (size_t)(q0 + r) * D_ + cg);
        Qs[r * ASTR + cg + 0] = vq.x * scale;
        Qs[r * ASTR + cg + 1] = vq.y * scale;
        Qs[r * ASTR + cg + 2] = vq.z * scale;
        Qs[r * ASTR + cg + 3] = vq.w * scale;
    }
    if (t < 64) { m_s[t] = -INFINITY; l_s[t] = 0.f; }

    float acc[4][4];
    #pragma unroll
    for (int i = 0; i < 4; i++)
        #pragma unroll
        for (int j = 0; j < 4; j++) acc[i][j] = 0.f;

    __syncthreads();

    for (int k0 = 0; k0 < L_; k0 += 64) {
        for (int i = t; i < 64 * 16; i += 256) {
            int r = i >> 4, cg = (i & 15) * 4;
            float4 vk = *(const float4*)(k + base + (size_t)(k0 + r) * D_ + cg);
            KPs[(cg + 0) * ASTR + r] = vk.x;
            KPs[(cg + 1) * ASTR + r] = vk.y;
            KPs[(cg + 2) * ASTR + r] = vk.z;
            KPs[(cg + 3) * ASTR + r] = vk.w;
            float4 vv = *(const float4*)(v + base + (size_t)(k0 + r) * D_ + cg);
            *(float4*)&Vs[r * ASTR + cg] = vv;
        }
        __syncthreads();

        float s[4][4];
        #pragma unroll
        for (int i = 0; i < 4; i++)
            #pragma unroll
            for (int j = 0; j < 4; j++) s[i][j] = 0.f;
        #pragma unroll 4
        for (int d = 0; d < 64; d++) {
            float4 bk = *(float4*)&KPs[d * ASTR + tx * 4];
            float a0 = Qs[(ty * 4 + 0) * ASTR + d];
            float a1 = Qs[(ty * 4 + 1) * ASTR + d];
            float a2 = Qs[(ty * 4 + 2) * ASTR + d];
            float a3 = Qs[(ty * 4 + 3) * ASTR + d];
            s[0][0] += a0 * bk.x; s[0][1] += a0 * bk.y; s[0][2] += a0 * bk.z; s[0][3] += a0 * bk.w;
            s[1][0] += a1 * bk.x; s[1][1] += a1 * bk.y; s[1][2] += a1 * bk.z; s[1][3] += a1 * bk.w;
            s[2][0] += a2 * bk.x; s[2][1] += a2 * bk.y; s[2][2] += a2 * bk.z; s[2][3] += a2 * bk.w;
            s[3][0] += a3 * bk.x; s[3][1] += a3 * bk.y; s[3][2] += a3 * bk.z; s[3][3] += a3 * bk.w;
        }
        #pragma unroll
        for (int i = 0; i < 4; i++) {
            float mx = fmaxf(fmaxf(s[i][0], s[i][1]), fmaxf(s[i][2], s[i][3]));
            red[(ty * 4 + i) * 16 + tx] = mx;
        }
        __syncthreads();
        if (t < 64) {
            float mt = red[t * 16];
            #pragma unroll
            for (int j = 1; j < 16; j++) mt = fmaxf(mt, red[t * 16 + j]);
            float mo = m_s[t];
            float mn = fmaxf(mo, mt);
            a_s[t] = expf(mo - mn);
            m_s[t] = mn;
        }
        __syncthreads();
        #pragma unroll
        for (int i = 0; i < 4; i++) {
            float mrow = m_s[ty * 4 + i];
            float p0 = expf(s[i][0] - mrow);
            float p1 = expf(s[i][1] - mrow);
            float p2 = expf(s[i][2] - mrow);
            float p3 = expf(s[i][3] - mrow);
            *(float4*)&KPs[(ty * 4 + i) * ASTR + tx * 4] = make_float4(p0, p1, p2, p3);
            red[(ty * 4 + i) * 16 + tx] = p0 + p1 + p2 + p3;
        }
        __syncthreads();
        if (t < 64) {
            float sum = 0.f;
            #pragma unroll
            for (int j = 0; j < 16; j++) sum += red[t * 16 + j];
            l_s[t] = l_s[t] * a_s[t] + sum;
        }
        float al[4];
        #pragma unroll
        for (int i = 0; i < 4; i++) al[i] = a_s[ty * 4 + i];
        #pragma unroll
        for (int i = 0; i < 4; i++)
            #pragma unroll
            for (int j = 0; j < 4; j++) acc[i][j] *= al[i];
        #pragma unroll 4
        for (int kk = 0; kk < 64; kk++) {
            float4 bv = *(float4*)&Vs[kk * ASTR + tx * 4];
            float p0 = KPs[(ty * 4 + 0) * ASTR + kk];
            float p1 = KPs[(ty * 4 + 1) * ASTR + kk];
            float p2 = KPs[(ty * 4 + 2) * ASTR + kk];
            float p3 = KPs[(ty * 4 + 3) * ASTR + kk];
            acc[0][0] += p0 * bv.x; acc[0][1] += p0 * bv.y; acc[0][2] += p0 * bv.z; acc[0][3] += p0 * bv.w;
            acc[1][0] += p1 * bv.x; acc[1][1] += p1 * bv.y; acc[1][2] += p1 * bv.z; acc[1][3] += p1 * bv.w;
            acc[2][0] += p2 * bv.x; acc[2][1] += p2 * bv.y; acc[2][2] += p2 * bv.z; acc[2][3] += p2 * bv.w;
            acc[3][0] += p3 * bv.x; acc[3][1] += p3 * bv.y; acc[3][2] += p3 * bv.z; acc[3][3] += p3 * bv.w;
        }
        __syncthreads();
    }

    #pragma unroll
    for (int i = 0; i < 4; i++) {
        float inv = 1.f / l_s[ty * 4 + i];
        float4 wv = make_float4(rtf32(acc[i][0] * inv), rtf32(acc[i][1] * inv),
                                rtf32(acc[i][2] * inv), rtf32(acc[i][3] * inv));
        *(float4*)(o + base + (size_t)(q0 + ty * 4 + i) * D_ + tx * 4) = wv;
    }
}

// ---------------- launch ----------------
extern "C" void kernel_launch(void* const* d_in, const int* in_sizes, int n_in,
                              void* d_out, int out_size) {
    const float* x     = (const float*)d_in[0];
    const float* pos   = (const float*)d_in[1];
    const float* ln1_g = (const float*)d_in[2];
    const float* ln1_b = (const float*)d_in[3];
    const float* Wq    = (const float*)d_in[4];
    const float* Wk    = (const float*)d_in[5];
    const float* Wv    = (const float*)d_in[6];
    const float* Wo    = (const float*)d_in[7];
    const float* bo    = (const float*)d_in[8];
    const float* ln2_g = (const float*)d_in[9];
    const float* ln2_b = (const float*)d_in[10];
    const float* W1    = (const float*)d_in[11];
    const float* b1    = (const float*)d_in[12];
    const float* W2    = (const float*)d_in[13];
    const float* b2    = (const float*)d_in[14];
    float* out = (float*)d_out;

    float *h, *q, *k, *v, *ao, *x2, *ff;
    float *wqT, *wkT, *wvT, *woT, *w1T, *w2T;
    cudaGetSymbolAddress((void**)&h,  g_h);
    cudaGetSymbolAddress((void**)&q,  g_q);
    cudaGetSymbolAddress((void**)&k,  g_k);
    cudaGetSymbolAddress((void**)&v,  g_v);
    cudaGetSymbolAddress((void**)&ao, g_ao);
    cudaGetSymbolAddress((void**)&x2, g_x2);
    cudaGetSymbolAddress((void**)&ff, g_ff);
    cudaGetSymbolAddress((void**)&wqT, g_wqT);
    cudaGetSymbolAddress((void**)&wkT, g_wkT);
    cudaGetSymbolAddress((void**)&wvT, g_wvT);
    cudaGetSymbolAddress((void**)&woT, g_woT);
    cudaGetSymbolAddress((void**)&w1T, g_w1T);
    cudaGetSymbolAddress((void**)&w2T, g_w2T);

    cudaFuncSetAttribute(gemm_mma, cudaFuncAttributeMaxDynamicSharedMemorySize, GEMM_SMEM_BYTES);
    int asmem = (3 * 64 * ASTR + 64 * 16 + 3 * 64) * (int)sizeof(float);
    cudaFuncSetAttribute(attn_kernel, cudaFuncAttributeMaxDynamicSharedMemorySize, asmem);

    const int ROWS = B_ * L_;   // 4096
    dim3 tb(32, 8);

    transpose_tf32<<<dim3(D_ / 32, D_ / 32), tb>>>(Wq, wqT, D_, D_);
    transpose_tf32<<<dim3(D_ / 32, D_ / 32), tb>>>(Wk, wkT, D_, D_);
    transpose_tf32<<<dim3(D_ / 32, D_ / 32), tb>>>(Wv, wvT, D_, D_);
    transpose_tf32<<<dim3(D_ / 32, D_ / 32), tb>>>(Wo, woT, D_, D_);
    transpose_tf32<<<dim3(FF_ / 32, D_ / 32), tb>>>(W1, w1T, D_, FF_);
    transpose_tf32<<<dim3(D_ / 32, FF_ / 32), tb>>>(W2, w2T, FF_, D_);

    // 1) h = round_tf32(LN1(x) + pos)
    ln_kernel<<<ROWS, 256>>>(x, ln1_g, ln1_b, pos, h);

    // 2-4) q/k/v
    {
        dim3 grid(D_ / 128, ROWS / 128);
        gemm_mma<<<grid, 256, GEMM_SMEM_BYTES>>>(h, wqT, nullptr, nullptr, q, ROWS, D_, D_, 0);
        gemm_mma<<<grid, 256, GEMM_SMEM_BYTES>>>(h, wkT, nullptr, nullptr, k, ROWS, D_, D_, 0);
        gemm_mma<<<grid, 256, GEMM_SMEM_BYTES>>>(h, wvT, nullptr, nullptr, v, ROWS, D_, D_, 0);
    }

    // 5) attention
    {
        dim3 grid(L_ / 64, B_ * H_);
        attn_kernel<<<grid, 256, asmem>>>(q, k, v, ao);
    }

    // 6) x2 = x + ao @ Wo + bo (exact fp32 residual)
    {
        dim3 grid(D_ / 128, ROWS / 128);
        gemm_mma<<<grid, 256, GEMM_SMEM_BYTES>>>(ao, woT, bo, x, x2, ROWS, D_, D_, 0);
    }

    // 7) h = round_tf32(LN2(x2))
    ln_kernel<<<ROWS, 256>>>(x2, ln2_g, ln2_b, nullptr, h);

    // 8) ff = round_tf32(gelu(h @ W1 + b1))
    {
        dim3 grid(FF_ / 128, ROWS / 128);
        gemm_mma<<<grid, 256, GEMM_SMEM_BYTES>>>(h, w1T, b1, nullptr, ff, ROWS, FF_, D_, 3);
    }

    // 9) out = x2 + ff @ W2 + b2
    {
        dim3 grid(D_ / 128, ROWS / 128);
        gemm_mma<<<grid, 256, GEMM_SMEM_BYTES>>>(ff, w2T, b2, x2, out, ROWS, D_, FF_, 0);
    }
}

// round 5
// speedup vs baseline: 2.4638x; 1.5019x over previous
#include <cuda_runtime.h>
#include <math.h>
#include <stdint.h>

#define B_ 2
#define L_ 2048
#define D_ 1024
#define H_ 16
#define DH_ 64
#define FF_ 4096
#define EPS_ 1e-5f

// ---------------- scratch (device globals) ----------------
__device__ float g_h[B_ * L_ * D_];
__device__ float g_q[B_ * L_ * D_];
__device__ float g_k[B_ * L_ * D_];
__device__ float g_v[B_ * L_ * D_];
__device__ float g_ao[B_ * L_ * D_];
__device__ float g_x2[B_ * L_ * D_];
__device__ float g_ff[B_ * L_ * FF_];
__device__ float g_wqT[D_ * D_];
__device__ float g_wkT[D_ * D_];
__device__ float g_wvT[D_ * D_];
__device__ float g_woT[D_ * D_];
__device__ float g_w1T[FF_ * D_];   // [FF][D] K-major
__device__ float g_w2T[D_ * FF_];   // [D][FF] K-major

// ---------------- helpers ----------------
__device__ __forceinline__ uint32_t smem_u32(const void* p) {
    uint32_t a;
    asm("{ .reg .u64 t; cvta.to.shared.u64 t, %1; cvt.u32.u64 %0, t; }" : "=r"(a) : "l"(p));
    return a;
}
__device__ __forceinline__ float rtf32(float x) {
    uint32_t u;
    asm("cvt.rna.tf32.f32 %0, %1;" : "=r"(u) : "f"(x));
    return __uint_as_float(u);
}
__device__ __forceinline__ void mma_tf32(float* c, const uint32_t* a, const uint32_t* b) {
    asm volatile(
        "mma.sync.aligned.m16n8k8.row.col.f32.tf32.tf32.f32 "
        "{%0,%1,%2,%3}, {%4,%5,%6,%7}, {%8,%9}, {%0,%1,%2,%3};"
        : "+f"(c[0]), "+f"(c[1]), "+f"(c[2]), "+f"(c[3])
        : "r"(a[0]), "r"(a[1]), "r"(a[2]), "r"(a[3]), "r"(b[0]), "r"(b[1]));
}

#define CP_ASYNC16(dst, src) \
    asm volatile("cp.async.cg.shared.global [%0], [%1], 16;" :: "r"(dst), "l"(src))
#define CP_COMMIT() asm volatile("cp.async.commit_group;" ::: "memory")
#define CP_WAIT(n)  asm volatile("cp.async.wait_group %0;" :: "n"(n) : "memory")

// ---------------- LayerNorm (+pos), output rounded to tf32 ----------------
__global__ void ln_kernel(const float* __restrict__ x,
                          const float* __restrict__ gamma,
                          const float* __restrict__ beta,
                          const float* __restrict__ pos,
                          float* __restrict__ out) {
    int row = blockIdx.x;
    int l = row & (L_ - 1);
    const float* xr = x + (size_t)row * D_;
    int t = threadIdx.x;
    float4 v = *(const float4*)(xr + t * 4);

    float s = v.x + v.y + v.z + v.w;
    float sq = v.x * v.x + v.y * v.y + v.z * v.z + v.w * v.w;
    #pragma unroll
    for (int o = 16; o > 0; o >>= 1) {
        s  += __shfl_down_sync(0xffffffffu, s,  o);
        sq += __shfl_down_sync(0xffffffffu, sq, o);
    }
    __shared__ float ss[8], sqs[8], stats[2];
    int wid = t >> 5, lane = t & 31;
    if (lane == 0) { ss[wid] = s; sqs[wid] = sq; }
    __syncthreads();
    if (t == 0) {
        float S = 0.f, SQ = 0.f;
        #pragma unroll
        for (int i = 0; i < 8; i++) { S += ss[i]; SQ += sqs[i]; }
        float mu = S / (float)D_;
        float var = SQ / (float)D_ - mu * mu;
        stats[0] = mu;
        stats[1] = rsqrtf(var + EPS_);
    }
    __syncthreads();
    float mu = stats[0], rs = stats[1];

    float4 g4 = *(const float4*)(gamma + t * 4);
    float4 b4 = *(const float4*)(beta + t * 4);
    float4 r;
    r.x = (v.x - mu) * rs * g4.x + b4.x;
    r.y = (v.y - mu) * rs * g4.y + b4.y;
    r.z = (v.z - mu) * rs * g4.z + b4.z;
    r.w = (v.w - mu) * rs * g4.w + b4.w;
    if (pos) {
        float4 p4 = *(const float4*)(pos + (size_t)l * D_ + t * 4);
        r.x += p4.x; r.y += p4.y; r.z += p4.z; r.w += p4.w;
    }
    r.x = rtf32(r.x); r.y = rtf32(r.y); r.z = rtf32(r.z); r.w = rtf32(r.w);
    *(float4*)(out + (size_t)row * D_ + t * 4) = r;
}

// ---------------- weight transpose + tf32 round: WT[n][k] = rtf32(W[k][n]) ----------------
__global__ void transpose_tf32(const float* __restrict__ W, float* __restrict__ WT, int K, int N) {
    __shared__ float tile[32][33];
    int n0 = blockIdx.x * 32, k0 = blockIdx.y * 32;
    int tx = threadIdx.x, ty = threadIdx.y;
    #pragma unroll
    for (int i = 0; i < 4; i++)
        tile[ty + 8 * i][tx] = W[(size_t)(k0 + ty + 8 * i) * N + n0 + tx];
    __syncthreads();
    #pragma unroll
    for (int i = 0; i < 4; i++)
        WT[(size_t)(n0 + ty + 8 * i) * K + k0 + tx] = rtf32(tile[tx][ty + 8 * i]);
}

// ---------------- tf32 mma.sync GEMM ----------------
// C[M,N] = A[M,K] @ BT[N,K]^T, both K-major, tf32-prerounded.
// flags: bit0 = gelu, bit1 = round output to tf32
#define AST 36
#define GEMM_SMEM_FLOATS (4 * 128 * AST + 128)
#define GEMM_SMEM_BYTES  (GEMM_SMEM_FLOATS * 4)

__global__ __launch_bounds__(256, 2)
void gemm_mma(const float* __restrict__ A, const float* __restrict__ BT,
              const float* __restrict__ bias, const float* __restrict__ addsrc,
              float* __restrict__ C, int M, int N, int K, int flags) {
    extern __shared__ float sm[];
    float* As0 = sm;
    float* Bs0 = sm + 128 * AST;
    float* As1 = sm + 2 * 128 * AST;
    float* Bs1 = sm + 3 * 128 * AST;
    float* bias_s = sm + 4 * 128 * AST;

    int t = threadIdx.x;
    int wid = t >> 5, lane = t & 31;
    int wm = wid & 1, wn = wid >> 1;
    int gid = lane >> 2, tig = lane & 3;
    int n0 = blockIdx.x * 128, m0 = blockIdx.y * 128;

    uint32_t sA[2] = { smem_u32(As0), smem_u32(As1) };
    uint32_t sB[2] = { smem_u32(Bs0), smem_u32(Bs1) };

    if (t < 32) {
        float4 bv = bias ? *(const float4*)(bias + n0 + t * 4) : make_float4(0.f, 0.f, 0.f, 0.f);
        *(float4*)(bias_s + t * 4) = bv;
    }

    int lrow = t >> 1;
    int lc4  = (t & 1) * 4;
    #define LOAD_TILE(buf, kk0) do { \
        _Pragma("unroll") \
        for (int j = 0; j < 4; j++) { \
            uint32_t off = (uint32_t)(lrow * AST + (lc4 + j) * 4) * 4u; \
            CP_ASYNC16(sA[buf] + off, A + (size_t)(m0 + lrow) * K + (kk0) + (lc4 + j) * 4); \
            CP_ASYNC16(sB[buf] + off, BT + (size_t)(n0 + lrow) * K + (kk0) + (lc4 + j) * 4); \
        } \
    } while (0)

    float acc[4][4][4];
    #pragma unroll
    for (int i = 0; i < 4; i++)
        #pragma unroll
        for (int j = 0; j < 4; j++)
            #pragma unroll
            for (int c = 0; c < 4; c++) acc[i][j][c] = 0.f;

    const int NS = K >> 5;
    LOAD_TILE(0, 0);
    CP_COMMIT();

    for (int s = 0; s < NS; s++) {
        if (s + 1 < NS) {
            LOAD_TILE((s + 1) & 1, (s + 1) << 5);
            CP_COMMIT();
            CP_WAIT(1);
        } else {
            CP_WAIT(0);
        }
        __syncthreads();

        const float* as = (s & 1) ? As1 : As0;
        const float* bs = (s & 1) ? Bs1 : Bs0;
        int arow = wm * 64 + gid;
        int bcol = wn * 32 + gid;

        #pragma unroll
        for (int kk = 0; kk < 4; kk++) {
            int kb = kk * 8 + tig;
            uint32_t af[4][4];
            #pragma unroll
            for (int mf = 0; mf < 4; mf++) {
                int r = arow + mf * 16;
                af[mf][0] = __float_as_uint(as[r * AST + kb]);
                af[mf][1] = __float_as_uint(as[(r + 8) * AST + kb]);
                af[mf][2] = __float_as_uint(as[r * AST + kb + 4]);
                af[mf][3] = __float_as_uint(as[(r + 8) * AST + kb + 4]);
            }
            uint32_t bf[4][2];
            #pragma unroll
            for (int nf = 0; nf < 4; nf++) {
                int c = bcol + nf * 8;
                bf[nf][0] = __float_as_uint(bs[c * AST + kb]);
                bf[nf][1] = __float_as_uint(bs[c * AST + kb + 4]);
            }
            #pragma unroll
            for (int mf = 0; mf < 4; mf++)
                #pragma unroll
                for (int nf = 0; nf < 4; nf++)
                    mma_tf32(acc[mf][nf], af[mf], bf[nf]);
        }
        __syncthreads();
    }

    bool do_gelu = (flags & 1), do_round = (flags & 2);
    int row_base = m0 + wm * 64 + gid;
    int colw = wn * 32;
    #pragma unroll
    for (int mf = 0; mf < 4; mf++) {
        #pragma unroll
        for (int rr = 0; rr < 2; rr++) {
            int grow = row_base + mf * 16 + rr * 8;
            size_t roff = (size_t)grow * N + n0 + colw;
            #pragma unroll
            for (int nf = 0; nf < 4; nf++) {
                int cl = colw + nf * 8 + tig * 2;
                float v0 = acc[mf][nf][rr * 2 + 0] + bias_s[cl];
                float v1 = acc[mf][nf][rr * 2 + 1] + bias_s[cl + 1];
                if (do_gelu) {
                    v0 = 0.5f * v0 * (1.f + erff(v0 * 0.70710678118654752f));
                    v1 = 0.5f * v1 * (1.f + erff(v1 * 0.70710678118654752f));
                }
                if (addsrc) {
                    float2 sv = *(const float2*)(addsrc + roff + nf * 8 + tig * 2);
                    v0 += sv.x; v1 += sv.y;
                }
                if (do_round) { v0 = rtf32(v0); v1 = rtf32(v1); }
                *(float2*)(C + roff + nf * 8 + tig * 2) = make_float2(v0, v1);
            }
        }
    }
    #undef LOAD_TILE
}

// ---------------- fused attention, tf32 mma (flash-style) ----------------
#define QST 68
#define VST 72
#define ATT_SMEM ((3 * 64 * QST + 64 * VST) * 4)

__global__ __launch_bounds__(128)
void attn_mma(const float* __restrict__ q,
              const float* __restrict__ k,
              const float* __restrict__ v,
              float* __restrict__ o) {
    extern __shared__ float sm[];
    float* Qs = sm;                    // [64][QST]  (q-row, d), pre-scaled
    float* Ks = sm + 64 * QST;         // [64][QST]  (kidx, d)
    float* Ps = sm + 2 * 64 * QST;     // [64][QST]  (q-row, kidx)
    float* Vs = sm + 3 * 64 * QST;     // [64][VST]  (kidx, d)

    int t = threadIdx.x;
    int w = t >> 5, lane = t & 31;
    int gid = lane >> 2, tig = lane & 3;
    int bh = blockIdx.y;
    int b = bh >> 4, h = bh & 15;
    int q0 = blockIdx.x * 64;
    int qrow = w * 16;
    size_t base = ((size_t)b * L_) * D_ + (size_t)h * DH_;
    const float scale = 0.125f;

    for (int i = t; i < 64 * 16; i += 128) {
        int r = i >> 4, c4 = i & 15;
        float4 vq = *(const float4*)(q + base + (size_t)(q0 + r) * D_ + c4 * 4);
        vq.x *= scale; vq.y *= scale; vq.z *= scale; vq.w *= scale;
        *(float4*)&Qs[r * QST + c4 * 4] = vq;
    }

    float oacc[8][4];
    #pragma unroll
    for (int i = 0; i < 8; i++)
        #pragma unroll
        for (int j = 0; j < 4; j++) oacc[i][j] = 0.f;
    float m0 = -INFINITY, m1 = -INFINITY, l0 = 0.f, l1 = 0.f;

    for (int k0 = 0; k0 < L_; k0 += 64) {
        __syncthreads();
        for (int i = t; i < 64 * 16; i += 128) {
            int r = i >> 4, c4 = i & 15;
            float4 vk = *(const float4*)(k + base + (size_t)(k0 + r) * D_ + c4 * 4);
            *(float4*)&Ks[r * QST + c4 * 4] = vk;
            float4 vv = *(const float4*)(v + base + (size_t)(k0 + r) * D_ + c4 * 4);
            *(float4*)&Vs[r * VST + c4 * 4] = vv;
        }
        __syncthreads();

        float sacc[8][4];
        #pragma unroll
        for (int i = 0; i < 8; i++)
            #pragma unroll
            for (int j = 0; j < 4; j++) sacc[i][j] = 0.f;
        #pragma unroll
        for (int ks = 0; ks < 8; ks++) {
            int kb = ks * 8 + tig;
            uint32_t af[4];
            af[0] = __float_as_uint(Qs[(qrow + gid) * QST + kb]);
            af[1] = __float_as_uint(Qs[(qrow + gid + 8) * QST + kb]);
            af[2] = __float_as_uint(Qs[(qrow + gid) * QST + kb + 4]);
            af[3] = __float_as_uint(Qs[(qrow + gid + 8) * QST + kb + 4]);
            #pragma unroll
            for (int nf = 0; nf < 8; nf++) {
                uint32_t bf[2];
                bf[0] = __float_as_uint(Ks[(nf * 8 + gid) * QST + kb]);
                bf[1] = __float_as_uint(Ks[(nf * 8 + gid) * QST + kb + 4]);
                mma_tf32(sacc[nf], af, bf);
            }
        }

        float mx0 = -INFINITY, mx1 = -INFINITY;
        #pragma unroll
        for (int nf = 0; nf < 8; nf++) {
            mx0 = fmaxf(mx0, fmaxf(sacc[nf][0], sacc[nf][1]));
            mx1 = fmaxf(mx1, fmaxf(sacc[nf][2], sacc[nf][3]));
        }
        mx0 = fmaxf(mx0, __shfl_xor_sync(0xffffffffu, mx0, 1));
        mx0 = fmaxf(mx0, __shfl_xor_sync(0xffffffffu, mx0, 2));
        mx1 = fmaxf(mx1, __shfl_xor_sync(0xffffffffu, mx1, 1));
        mx1 = fmaxf(mx1, __shfl_xor_sync(0xffffffffu, mx1, 2));
        float mn0 = fmaxf(m0, mx0), mn1 = fmaxf(m1, mx1);
        float al0 = __expf(m0 - mn0), al1 = __expf(m1 - mn1);
        m0 = mn0; m1 = mn1;

        float sum0 = 0.f, sum1 = 0.f;
        #pragma unroll
        for (int nf = 0; nf < 8; nf++) {
            float p00 = __expf(sacc[nf][0] - m0);
            float p01 = __expf(sacc[nf][1] - m0);
            float p10 = __expf(sacc[nf][2] - m1);
            float p11 = __expf(sacc[nf][3] - m1);
            sum0 += p00 + p01;
            sum1 += p10 + p11;
            *(float2*)&Ps[(qrow + gid) * QST + nf * 8 + tig * 2] =
                make_float2(rtf32(p00), rtf32(p01));
            *(float2*)&Ps[(qrow + gid + 8) * QST + nf * 8 + tig * 2] =
                make_float2(rtf32(p10), rtf32(p11));
        }
        sum0 += __shfl_xor_sync(0xffffffffu, sum0, 1);
        sum0 += __shfl_xor_sync(0xffffffffu, sum0, 2);
        sum1 += __shfl_xor_sync(0xffffffffu, sum1, 1);
        sum1 += __shfl_xor_sync(0xffffffffu, sum1, 2);
        l0 = l0 * al0 + sum0;
        l1 = l1 * al1 + sum1;

        #pragma unroll
        for (int nf = 0; nf < 8; nf++) {
            oacc[nf][0] *= al0; oacc[nf][1] *= al0;
            oacc[nf][2] *= al1; oacc[nf][3] *= al1;
        }
        __syncwarp();

        #pragma unroll
        for (int ks = 0; ks < 8; ks++) {
            int kb = ks * 8 + tig;
            uint32_t af[4];
            af[0] = __float_as_uint(Ps[(qrow + gid) * QST + kb]);
            af[1] = __float_as_uint(Ps[(qrow + gid + 8) * QST + kb]);
            af[2] = __float_as_uint(Ps[(qrow + gid) * QST + kb + 4]);
            af[3] = __float_as_uint(Ps[(qrow + gid + 8) * QST + kb + 4]);
            #pragma unroll
            for (int nf = 0; nf < 8; nf++) {
                uint32_t bf[2];
                bf[0] = __float_as_uint(Vs[kb * VST + nf * 8 + gid]);
                bf[1] = __float_as_uint(Vs[(kb + 4) * VST + nf * 8 + gid]);
                mma_tf32(oacc[nf], af, bf);
            }
        }
    }

    float inv0 = 1.f / l0, inv1 = 1.f / l1;
    size_t r0off = base + (size_t)(q0 + qrow + gid) * D_;
    size_t r1off = base + (size_t)(q0 + qrow + gid + 8) * D_;
    #pragma unroll
    for (int nf = 0; nf < 8; nf++) {
        int c = nf * 8 + tig * 2;
        *(float2*)(o + r0off + c) = make_float2(rtf32(oacc[nf][0] * inv0), rtf32(oacc[nf][1] * inv0));
        *(float2*)(o + r1off + c) = make_float2(rtf32(oacc[nf][2] * inv1), rtf32(oacc[nf][3] * inv1));
    }
}

// ---------------- launch ----------------
extern "C" void kernel_launch(void* const* d_in, const int* in_sizes, int n_in,
                              void* d_out, int out_size) {
    const float* x     = (const float*)d_in[0];
    const float* pos   = (const float*)d_in[1];
    const float* ln1_g = (const float*)d_in[2];
    const float* ln1_b = (const float*)d_in[3];
    const float* Wq    = (const float*)d_in[4];
    const float* Wk    = (const float*)d_in[5];
    const float* Wv    = (const float*)d_in[6];
    const float* Wo    = (const float*)d_in[7];
    const float* bo    = (const float*)d_in[8];
    const float* ln2_g = (const float*)d_in[9];
    const float* ln2_b = (const float*)d_in[10];
    const float* W1    = (const float*)d_in[11];
    const float* b1    = (const float*)d_in[12];
    const float* W2    = (const float*)d_in[13];
    const float* b2    = (const float*)d_in[14];
    float* out = (float*)d_out;

    float *h, *q, *k, *v, *ao, *x2, *ff;
    float *wqT, *wkT, *wvT, *woT, *w1T, *w2T;
    cudaGetSymbolAddress((void**)&h,  g_h);
    cudaGetSymbolAddress((void**)&q,  g_q);
    cudaGetSymbolAddress((void**)&k,  g_k);
    cudaGetSymbolAddress((void**)&v,  g_v);
    cudaGetSymbolAddress((void**)&ao, g_ao);
    cudaGetSymbolAddress((void**)&x2, g_x2);
    cudaGetSymbolAddress((void**)&ff, g_ff);
    cudaGetSymbolAddress((void**)&wqT, g_wqT);
    cudaGetSymbolAddress((void**)&wkT, g_wkT);
    cudaGetSymbolAddress((void**)&wvT, g_wvT);
    cudaGetSymbolAddress((void**)&woT, g_woT);
    cudaGetSymbolAddress((void**)&w1T, g_w1T);
    cudaGetSymbolAddress((void**)&w2T, g_w2T);

    cudaFuncSetAttribute(gemm_mma, cudaFuncAttributeMaxDynamicSharedMemorySize, GEMM_SMEM_BYTES);
    cudaFuncSetAttribute(attn_mma, cudaFuncAttributeMaxDynamicSharedMemorySize, ATT_SMEM);

    const int ROWS = B_ * L_;   // 4096
    dim3 tb(32, 8);

    transpose_tf32<<<dim3(D_ / 32, D_ / 32), tb>>>(Wq, wqT, D_, D_);
    transpose_tf32<<<dim3(D_ / 32, D_ / 32), tb>>>(Wk, wkT, D_, D_);
    transpose_tf32<<<dim3(D_ / 32, D_ / 32), tb>>>(Wv, wvT, D_, D_);
    transpose_tf32<<<dim3(D_ / 32, D_ / 32), tb>>>(Wo, woT, D_, D_);
    transpose_tf32<<<dim3(FF_ / 32, D_ / 32), tb>>>(W1, w1T, D_, FF_);
    transpose_tf32<<<dim3(D_ / 32, FF_ / 32), tb>>>(W2, w2T, FF_, D_);

    // 1) h = round_tf32(LN1(x) + pos)
    ln_kernel<<<ROWS, 256>>>(x, ln1_g, ln1_b, pos, h);

    // 2-4) q/k/v (tf32-rounded outputs -> valid mma operands in attention)
    {
        dim3 grid(D_ / 128, ROWS / 128);
        gemm_mma<<<grid, 256, GEMM_SMEM_BYTES>>>(h, wqT, nullptr, nullptr, q, ROWS, D_, D_, 2);
        gemm_mma<<<grid, 256, GEMM_SMEM_BYTES>>>(h, wkT, nullptr, nullptr, k, ROWS, D_, D_, 2);
        gemm_mma<<<grid, 256, GEMM_SMEM_BYTES>>>(h, wvT, nullptr, nullptr, v, ROWS, D_, D_, 2);
    }

    // 5) attention (tf32 mma flash)
    {
        dim3 grid(L_ / 64, B_ * H_);
        attn_mma<<<grid, 128, ATT_SMEM>>>(q, k, v, ao);
    }

    // 6) x2 = x + ao @ Wo + bo (exact fp32 residual)
    {
        dim3 grid(D_ / 128, ROWS / 128);
        gemm_mma<<<grid, 256, GEMM_SMEM_BYTES>>>(ao, woT, bo, x, x2, ROWS, D_, D_, 0);
    }

    // 7) h = round_tf32(LN2(x2))
    ln_kernel<<<ROWS, 256>>>(x2, ln2_g, ln2_b, nullptr, h);

    // 8) ff = round_tf32(gelu(h @ W1 + b1))
    {
        dim3 grid(FF_ / 128, ROWS / 128);
        gemm_mma<<<grid, 256, GEMM_SMEM_BYTES>>>(h, w1T, b1, nullptr, ff, ROWS, FF_, D_, 3);
    }

    // 9) out = x2 + ff @ W2 + b2
    {
        dim3 grid(D_ / 128, ROWS / 128);
        gemm_mma<<<grid, 256, GEMM_SMEM_BYTES>>>(ff, w2T, b2, x2, out, ROWS, D_, FF_, 0);
    }
}

// round 6
// speedup vs baseline: 2.7522x; 1.1171x over previous
#include <cuda_runtime.h>
#include <math.h>
#include <stdint.h>

#define B_ 2
#define L_ 2048
#define D_ 1024
#define H_ 16
#define DH_ 64
#define FF_ 4096
#define EPS_ 1e-5f
#define D3_ 3072

// ---------------- scratch (device globals) ----------------
__device__ float g_h[B_ * L_ * D_];
__device__ float g_qkv[B_ * L_ * D3_];     // fused q|k|v, row stride 3072
__device__ float g_ao[B_ * L_ * D_];
__device__ float g_x2[B_ * L_ * D_];
__device__ float g_ff[B_ * L_ * FF_];
__device__ float g_wqkvT[D3_ * D_];        // [3072][1024] K-major (q rows 0-1023, k, v)
__device__ float g_woT[D_ * D_];
__device__ float g_w1T[FF_ * D_];          // [FF][D] K-major
__device__ float g_w2T[D_ * FF_];          // [D][FF] K-major

// ---------------- helpers ----------------
__device__ __forceinline__ uint32_t smem_u32(const void* p) {
    uint32_t a;
    asm("{ .reg .u64 t; cvta.to.shared.u64 t, %1; cvt.u32.u64 %0, t; }" : "=r"(a) : "l"(p));
    return a;
}
__device__ __forceinline__ float rtf32(float x) {
    uint32_t u;
    asm("cvt.rna.tf32.f32 %0, %1;" : "=r"(u) : "f"(x));
    return __uint_as_float(u);
}
__device__ __forceinline__ void mma_tf32(float* c, const uint32_t* a, const uint32_t* b) {
    asm volatile(
        "mma.sync.aligned.m16n8k8.row.col.f32.tf32.tf32.f32 "
        "{%0,%1,%2,%3}, {%4,%5,%6,%7}, {%8,%9}, {%0,%1,%2,%3};"
        : "+f"(c[0]), "+f"(c[1]), "+f"(c[2]), "+f"(c[3])
        : "r"(a[0]), "r"(a[1]), "r"(a[2]), "r"(a[3]), "r"(b[0]), "r"(b[1]));
}
__device__ __forceinline__ void ldsm_x4(uint32_t* r, uint32_t addr) {
    asm volatile("ldmatrix.sync.aligned.m8n8.x4.shared.b16 {%0,%1,%2,%3}, [%4];"
        : "=r"(r[0]), "=r"(r[1]), "=r"(r[2]), "=r"(r[3]) : "r"(addr));
}

#define CP_ASYNC16(dst, src) \
    asm volatile("cp.async.cg.shared.global [%0], [%1], 16;" :: "r"(dst), "l"(src))
#define CP_COMMIT() asm volatile("cp.async.commit_group;" ::: "memory")
#define CP_WAIT(n)  asm volatile("cp.async.wait_group %0;" :: "n"(n) : "memory")

// ---------------- LayerNorm (+pos), output rounded to tf32 ----------------
__global__ void ln_kernel(const float* __restrict__ x,
                          const float* __restrict__ gamma,
                          const float* __restrict__ beta,
                          const float* __restrict__ pos,
                          float* __restrict__ out) {
    int row = blockIdx.x;
    int l = row & (L_ - 1);
    const float* xr = x + (size_t)row * D_;
    int t = threadIdx.x;
    float4 v = *(const float4*)(xr + t * 4);

    float s = v.x + v.y + v.z + v.w;
    float sq = v.x * v.x + v.y * v.y + v.z * v.z + v.w * v.w;
    #pragma unroll
    for (int o = 16; o > 0; o >>= 1) {
        s  += __shfl_down_sync(0xffffffffu, s,  o);
        sq += __shfl_down_sync(0xffffffffu, sq, o);
    }
    __shared__ float ss[8], sqs[8], stats[2];
    int wid = t >> 5, lane = t & 31;
    if (lane == 0) { ss[wid] = s; sqs[wid] = sq; }
    __syncthreads();
    if (t == 0) {
        float S = 0.f, SQ = 0.f;
        #pragma unroll
        for (int i = 0; i < 8; i++) { S += ss[i]; SQ += sqs[i]; }
        float mu = S / (float)D_;
        float var = SQ / (float)D_ - mu * mu;
        stats[0] = mu;
        stats[1] = rsqrtf(var + EPS_);
    }
    __syncthreads();
    float mu = stats[0], rs = stats[1];

    float4 g4 = *(const float4*)(gamma + t * 4);
    float4 b4 = *(const float4*)(beta + t * 4);
    float4 r;
    r.x = (v.x - mu) * rs * g4.x + b4.x;
    r.y = (v.y - mu) * rs * g4.y + b4.y;
    r.z = (v.z - mu) * rs * g4.z + b4.z;
    r.w = (v.w - mu) * rs * g4.w + b4.w;
    if (pos) {
        float4 p4 = *(const float4*)(pos + (size_t)l * D_ + t * 4);
        r.x += p4.x; r.y += p4.y; r.z += p4.z; r.w += p4.w;
    }
    r.x = rtf32(r.x); r.y = rtf32(r.y); r.z = rtf32(r.z); r.w = rtf32(r.w);
    *(float4*)(out + (size_t)row * D_ + t * 4) = r;
}

// ---------------- weight transpose + tf32 round: WT[n][k] = rtf32(W[k][n]) ----------------
__global__ void transpose_tf32(const float* __restrict__ W, float* __restrict__ WT, int K, int N) {
    __shared__ float tile[32][33];
    int n0 = blockIdx.x * 32, k0 = blockIdx.y * 32;
    int tx = threadIdx.x, ty = threadIdx.y;
    #pragma unroll
    for (int i = 0; i < 4; i++)
        tile[ty + 8 * i][tx] = W[(size_t)(k0 + ty + 8 * i) * N + n0 + tx];
    __syncthreads();
    #pragma unroll
    for (int i = 0; i < 4; i++)
        WT[(size_t)(n0 + ty + 8 * i) * K + k0 + tx] = rtf32(tile[tx][ty + 8 * i]);
}

// ---------------- tf32 mma.sync GEMM (ldmatrix mainloop) ----------------
// C[M,N] = A[M,K] @ BT[N,K]^T, both K-major, tf32-prerounded.
// flags: bit0 = gelu, bit1 = round output to tf32
#define AST 36
#define GEMM_SMEM_FLOATS (4 * 128 * AST + 128)
#define GEMM_SMEM_BYTES  (GEMM_SMEM_FLOATS * 4)

__global__ __launch_bounds__(256, 2)
void gemm_mma(const float* __restrict__ A, const float* __restrict__ BT,
              const float* __restrict__ bias, const float* __restrict__ addsrc,
              float* __restrict__ C, int M, int N, int K, int flags) {
    extern __shared__ float sm[];
    float* bias_s = sm + 4 * 128 * AST;

    int t = threadIdx.x;
    int wid = t >> 5, lane = t & 31;
    int wm = wid & 1, wn = wid >> 1;
    int gid = lane >> 2, tig = lane & 3;
    int n0 = blockIdx.x * 128, m0 = blockIdx.y * 128;

    uint32_t sA[2] = { smem_u32(sm),               smem_u32(sm + 2 * 128 * AST) };
    uint32_t sB[2] = { smem_u32(sm + 128 * AST),   smem_u32(sm + 3 * 128 * AST) };

    if (t < 32) {
        float4 bv = bias ? *(const float4*)(bias + n0 + t * 4) : make_float4(0.f, 0.f, 0.f, 0.f);
        *(float4*)(bias_s + t * 4) = bv;
    }

    // ldmatrix per-lane byte offsets (relative to buffer base), per mf / nf-pair
    int rsel = lane & 7;
    int t01  = (lane >> 3) & 1;   // tsel bit0
    int t23  = (lane >> 4) & 1;   // tsel bit1
    uint32_t aoff[4], boff[2];
    #pragma unroll
    for (int mf = 0; mf < 4; mf++)
        aoff[mf] = (uint32_t)(((wm * 64 + mf * 16 + t01 * 8 + rsel) * AST + t23 * 4) * 4);
    #pragma unroll
    for (int nf2 = 0; nf2 < 2; nf2++)
        boff[nf2] = (uint32_t)(((wn * 32 + nf2 * 16 + t23 * 8 + rsel) * AST + t01 * 4) * 4);

    // loader: tile is 128 rows x 32 cols, 8 float4/row, 2 threads/row x 4 float4 each
    int lrow = t >> 1;
    int lc4  = (t & 1) * 4;
    #define LOAD_TILE(buf, kk0) do { \
        _Pragma("unroll") \
        for (int j = 0; j < 4; j++) { \
            uint32_t off = (uint32_t)(lrow * AST + (lc4 + j) * 4) * 4u; \
            CP_ASYNC16(sA[buf] + off, A + (size_t)(m0 + lrow) * K + (kk0) + (lc4 + j) * 4); \
            CP_ASYNC16(sB[buf] + off, BT + (size_t)(n0 + lrow) * K + (kk0) + (lc4 + j) * 4); \
        } \
        CP_COMMIT(); \
    } while (0)

    float acc[4][4][4];
    #pragma unroll
    for (int i = 0; i < 4; i++)
        #pragma unroll
        for (int j = 0; j < 4; j++)
            #pragma unroll
            for (int c = 0; c < 4; c++) acc[i][j][c] = 0.f;

    const int NS = K >> 5;
    LOAD_TILE(0, 0);

    for (int s = 0; s < NS; s++) {
        CP_WAIT(0);
        __syncthreads();
        if (s + 1 < NS) LOAD_TILE((s + 1) & 1, (s + 1) << 5);

        int b = s & 1;
        #pragma unroll
        for (int kk = 0; kk < 4; kk++) {
            uint32_t kadd = (uint32_t)(kk * 32);
            uint32_t af[4][4];
            #pragma unroll
            for (int mf = 0; mf < 4; mf++)
                ldsm_x4(af[mf], sA[b] + aoff[mf] + kadd);
            uint32_t bf[8];
            ldsm_x4(bf,     sB[b] + boff[0] + kadd);
            ldsm_x4(bf + 4, sB[b] + boff[1] + kadd);
            #pragma unroll
            for (int mf = 0; mf < 4; mf++)
                #pragma unroll
                for (int nf = 0; nf < 4; nf++)
                    mma_tf32(acc[mf][nf], af[mf], bf + nf * 2);
        }
    }

    bool do_gelu = (flags & 1), do_round = (flags & 2);
    int row_base = m0 + wm * 64 + gid;
    int colw = wn * 32;
    #pragma unroll
    for (int mf = 0; mf < 4; mf++) {
        #pragma unroll
        for (int rr = 0; rr < 2; rr++) {
            int grow = row_base + mf * 16 + rr * 8;
            size_t roff = (size_t)grow * N + n0 + colw;
            #pragma unroll
            for (int nf = 0; nf < 4; nf++) {
                int cl = colw + nf * 8 + tig * 2;
                float v0 = acc[mf][nf][rr * 2 + 0] + bias_s[cl];
                float v1 = acc[mf][nf][rr * 2 + 1] + bias_s[cl + 1];
                if (do_gelu) {
                    v0 = 0.5f * v0 * (1.f + erff(v0 * 0.70710678118654752f));
                    v1 = 0.5f * v1 * (1.f + erff(v1 * 0.70710678118654752f));
                }
                if (addsrc) {
                    float2 sv = *(const float2*)(addsrc + roff + nf * 8 + tig * 2);
                    v0 += sv.x; v1 += sv.y;
                }
                if (do_round) { v0 = rtf32(v0); v1 = rtf32(v1); }
                *(float2*)(C + roff + nf * 8 + tig * 2) = make_float2(v0, v1);
            }
        }
    }
    #undef LOAD_TILE
}

// ---------------- fused attention, tf32 mma (flash-style) ----------------
// reads fused qkv buffer [B*L][3072]: q at col h*64, k at 1024+h*64, v at 2048+h*64
#define QST 68
#define VST 72
#define ATT_SMEM ((3 * 64 * QST + 64 * VST) * 4)

__global__ __launch_bounds__(128)
void attn_mma(const float* __restrict__ qkv, float* __restrict__ o) {
    extern __shared__ float sm[];
    float* Qs = sm;                    // [64][QST]  (q-row, d), pre-scaled
    float* Ks = sm + 64 * QST;         // [64][QST]  (kidx, d)
    float* Ps = sm + 2 * 64 * QST;     // [64][QST]  (q-row, kidx)
    float* Vs = sm + 3 * 64 * QST;     // [64][VST]  (kidx, d)

    int t = threadIdx.x;
    int w = t >> 5, lane = t & 31;
    int gid = lane >> 2, tig = lane & 3;
    int bh = blockIdx.y;
    int b = bh >> 4, h = bh & 15;
    int q0 = blockIdx.x * 64;
    int qrow = w * 16;
    size_t qbase = ((size_t)b * L_) * D3_ + (size_t)h * DH_;
    size_t obase = ((size_t)b * L_) * D_ + (size_t)h * DH_;
    const float scale = 0.125f;

    for (int i = t; i < 64 * 16; i += 128) {
        int r = i >> 4, c4 = i & 15;
        float4 vq = *(const float4*)(qkv + qbase + (size_t)(q0 + r) * D3_ + c4 * 4);
        vq.x *= scale; vq.y *= scale; vq.z *= scale; vq.w *= scale;
        *(float4*)&Qs[r * QST + c4 * 4] = vq;
    }

    float oacc[8][4];
    #pragma unroll
    for (int i = 0; i < 8; i++)
        #pragma unroll
        for (int j = 0; j < 4; j++) oacc[i][j] = 0.f;
    float m0 = -INFINITY, m1 = -INFINITY, l0 = 0.f, l1 = 0.f;

    for (int k0 = 0; k0 < L_; k0 += 64) {
        __syncthreads();
        for (int i = t; i < 64 * 16; i += 128) {
            int r = i >> 4, c4 = i & 15;
            float4 vk = *(const float4*)(qkv + qbase + 1024 + (size_t)(k0 + r) * D3_ + c4 * 4);
            *(float4*)&Ks[r * QST + c4 * 4] = vk;
            float4 vv = *(const float4*)(qkv + qbase + 2048 + (size_t)(k0 + r) * D3_ + c4 * 4);
            *(float4*)&Vs[r * VST + c4 * 4] = vv;
        }
        __syncthreads();

        float sacc[8][4];
        #pragma unroll
        for (int i = 0; i < 8; i++)
            #pragma unroll
            for (int j = 0; j < 4; j++) sacc[i][j] = 0.f;
        #pragma unroll
        for (int ks = 0; ks < 8; ks++) {
            int kb = ks * 8 + tig;
            uint32_t af[4];
            af[0] = __float_as_uint(Qs[(qrow + gid) * QST + kb]);
            af[1] = __float_as_uint(Qs[(qrow + gid + 8) * QST + kb]);
            af[2] = __float_as_uint(Qs[(qrow + gid) * QST + kb + 4]);
            af[3] = __float_as_uint(Qs[(qrow + gid + 8) * QST + kb + 4]);
            #pragma unroll
            for (int nf = 0; nf < 8; nf++) {
                uint32_t bf[2];
                bf[0] = __float_as_uint(Ks[(nf * 8 + gid) * QST + kb]);
                bf[1] = __float_as_uint(Ks[(nf * 8 + gid) * QST + kb + 4]);
                mma_tf32(sacc[nf], af, bf);
            }
        }

        float mx0 = -INFINITY, mx1 = -INFINITY;
        #pragma unroll
        for (int nf = 0; nf < 8; nf++) {
            mx0 = fmaxf(mx0, fmaxf(sacc[nf][0], sacc[nf][1]));
            mx1 = fmaxf(mx1, fmaxf(sacc[nf][2], sacc[nf][3]));
        }
        mx0 = fmaxf(mx0, __shfl_xor_sync(0xffffffffu, mx0, 1));
        mx0 = fmaxf(mx0, __shfl_xor_sync(0xffffffffu, mx0, 2));
        mx1 = fmaxf(mx1, __shfl_xor_sync(0xffffffffu, mx1, 1));
        mx1 = fmaxf(mx1, __shfl_xor_sync(0xffffffffu, mx1, 2));
        float mn0 = fmaxf(m0, mx0), mn1 = fmaxf(m1, mx1);
        float al0 = __expf(m0 - mn0), al1 = __expf(m1 - mn1);
        m0 = mn0; m1 = mn1;

        float sum0 = 0.f, sum1 = 0.f;
        #pragma unroll
        for (int nf = 0; nf < 8; nf++) {
            float p00 = __expf(sacc[nf][0] - m0);
            float p01 = __expf(sacc[nf][1] - m0);
            float p10 = __expf(sacc[nf][2] - m1);
            float p11 = __expf(sacc[nf][3] - m1);
            sum0 += p00 + p01;
            sum1 += p10 + p11;
            *(float2*)&Ps[(qrow + gid) * QST + nf * 8 + tig * 2] =
                make_float2(rtf32(p00), rtf32(p01));
            *(float2*)&Ps[(qrow + gid + 8) * QST + nf * 8 + tig * 2] =
                make_float2(rtf32(p10), rtf32(p11));
        }
        sum0 += __shfl_xor_sync(0xffffffffu, sum0, 1);
        sum0 += __shfl_xor_sync(0xffffffffu, sum0, 2);
        sum1 += __shfl_xor_sync(0xffffffffu, sum1, 1);
        sum1 += __shfl_xor_sync(0xffffffffu, sum1, 2);
        l0 = l0 * al0 + sum0;
        l1 = l1 * al1 + sum1;

        #pragma unroll
        for (int nf = 0; nf < 8; nf++) {
            oacc[nf][0] *= al0; oacc[nf][1] *= al0;
            oacc[nf][2] *= al1; oacc[nf][3] *= al1;
        }
        __syncwarp();

        #pragma unroll
        for (int ks = 0; ks < 8; ks++) {
            int kb = ks * 8 + tig;
            uint32_t af[4];
            af[0] = __float_as_uint(Ps[(qrow + gid) * QST + kb]);
            af[1] = __float_as_uint(Ps[(qrow + gid + 8) * QST + kb]);
            af[2] = __float_as_uint(Ps[(qrow + gid) * QST + kb + 4]);
            af[3] = __float_as_uint(Ps[(qrow + gid + 8) * QST + kb + 4]);
            #pragma unroll
            for (int nf = 0; nf < 8; nf++) {
                uint32_t bf[2];
                bf[0] = __float_as_uint(Vs[kb * VST + nf * 8 + gid]);
                bf[1] = __float_as_uint(Vs[(kb + 4) * VST + nf * 8 + gid]);
                mma_tf32(oacc[nf], af, bf);
            }
        }
    }

    float inv0 = 1.f / l0, inv1 = 1.f / l1;
    size_t r0off = obase + (size_t)(q0 + qrow + gid) * D_;
    size_t r1off = obase + (size_t)(q0 + qrow + gid + 8) * D_;
    #pragma unroll
    for (int nf = 0; nf < 8; nf++) {
        int c = nf * 8 + tig * 2;
        *(float2*)(o + r0off + c) = make_float2(rtf32(oacc[nf][0] * inv0), rtf32(oacc[nf][1] * inv0));
        *(float2*)(o + r1off + c) = make_float2(rtf32(oacc[nf][2] * inv1), rtf32(oacc[nf][3] * inv1));
    }
}

// ---------------- launch ----------------
extern "C" void kernel_launch(void* const* d_in, const int* in_sizes, int n_in,
                              void* d_out, int out_size) {
    const float* x     = (const float*)d_in[0];
    const float* pos   = (const float*)d_in[1];
    const float* ln1_g = (const float*)d_in[2];
    const float* ln1_b = (const float*)d_in[3];
    const float* Wq    = (const float*)d_in[4];
    const float* Wk    = (const float*)d_in[5];
    const float* Wv    = (const float*)d_in[6];
    const float* Wo    = (const float*)d_in[7];
    const float* bo    = (const float*)d_in[8];
    const float* ln2_g = (const float*)d_in[9];
    const float* ln2_b = (const float*)d_in[10];
    const float* W1    = (const float*)d_in[11];
    const float* b1    = (const float*)d_in[12];
    const float* W2    = (const float*)d_in[13];
    const float* b2    = (const float*)d_in[14];
    float* out = (float*)d_out;

    float *h, *qkv, *ao, *x2, *ff;
    float *wqkvT, *woT, *w1T, *w2T;
    cudaGetSymbolAddress((void**)&h,   g_h);
    cudaGetSymbolAddress((void**)&qkv, g_qkv);
    cudaGetSymbolAddress((void**)&ao,  g_ao);
    cudaGetSymbolAddress((void**)&x2,  g_x2);
    cudaGetSymbolAddress((void**)&ff,  g_ff);
    cudaGetSymbolAddress((void**)&wqkvT, g_wqkvT);
    cudaGetSymbolAddress((void**)&woT, g_woT);
    cudaGetSymbolAddress((void**)&w1T, g_w1T);
    cudaGetSymbolAddress((void**)&w2T, g_w2T);

    cudaFuncSetAttribute(gemm_mma, cudaFuncAttributeMaxDynamicSharedMemorySize, GEMM_SMEM_BYTES);
    cudaFuncSetAttribute(attn_mma, cudaFuncAttributeMaxDynamicSharedMemorySize, ATT_SMEM);

    const int ROWS = B_ * L_;   // 4096
    dim3 tb(32, 8);

    transpose_tf32<<<dim3(D_ / 32, D_ / 32), tb>>>(Wq, wqkvT,                 D_, D_);
    transpose_tf32<<<dim3(D_ / 32, D_ / 32), tb>>>(Wk, wqkvT + D_ * D_,       D_, D_);
    transpose_tf32<<<dim3(D_ / 32, D_ / 32), tb>>>(Wv, wqkvT + 2 * D_ * D_,   D_, D_);
    transpose_tf32<<<dim3(D_ / 32, D_ / 32), tb>>>(Wo, woT, D_, D_);
    transpose_tf32<<<dim3(FF_ / 32, D_ / 32), tb>>>(W1, w1T, D_, FF_);
    transpose_tf32<<<dim3(D_ / 32, FF_ / 32), tb>>>(W2, w2T, FF_, D_);

    // 1) h = round_tf32(LN1(x) + pos)
    ln_kernel<<<ROWS, 256>>>(x, ln1_g, ln1_b, pos, h);

    // 2) fused qkv = h @ [Wq|Wk|Wv]  (tf32-rounded outputs)
    {
        dim3 grid(D3_ / 128, ROWS / 128);
        gemm_mma<<<grid, 256, GEMM_SMEM_BYTES>>>(h, wqkvT, nullptr, nullptr, qkv, ROWS, D3_, D_, 2);
    }

    // 3) attention (tf32 mma flash)
    {
        dim3 grid(L_ / 64, B_ * H_);
        attn_mma<<<grid, 128, ATT_SMEM>>>(qkv, ao);
    }

    // 4) x2 = x + ao @ Wo + bo (exact fp32 residual)
    {
        dim3 grid(D_ / 128, ROWS / 128);
        gemm_mma<<<grid, 256, GEMM_SMEM_BYTES>>>(ao, woT, bo, x, x2, ROWS, D_, D_, 0);
    }

    // 5) h = round_tf32(LN2(x2))
    ln_kernel<<<ROWS, 256>>>(x2, ln2_g, ln2_b, nullptr, h);

    // 6) ff = round_tf32(gelu(h @ W1 + b1))
    {
        dim3 grid(FF_ / 128, ROWS / 128);
        gemm_mma<<<grid, 256, GEMM_SMEM_BYTES>>>(h, w1T, b1, nullptr, ff, ROWS, FF_, D_, 3);
    }

    // 7) out = x2 + ff @ W2 + b2
    {
        dim3 grid(D_ / 128, ROWS / 128);
        gemm_mma<<<grid, 256, GEMM_SMEM_BYTES>>>(ff, w2T, b2, x2, out, ROWS, D_, FF_, 0);
    }
}

// round 7
// speedup vs baseline: 3.2518x; 1.1815x over previous
#include <cuda_runtime.h>
#include <math.h>
#include <stdint.h>

#define B_ 2
#define L_ 2048
#define D_ 1024
#define H_ 16
#define DH_ 64
#define FF_ 4096
#define EPS_ 1e-5f
#define D3_ 3072

// ---------------- scratch (device globals) ----------------
__device__ float g_h[B_ * L_ * D_];
__device__ float g_qkv[B_ * L_ * D3_];     // fused q|k|v, row stride 3072
__device__ float g_ao[B_ * L_ * D_];
__device__ float g_x2[B_ * L_ * D_];
__device__ float g_ff[B_ * L_ * FF_];
__device__ float g_wqkvT[D3_ * D_];        // [3072][1024] K-major (q rows 0-1023, k, v)
__device__ float g_woT[D_ * D_];
__device__ float g_w1T[FF_ * D_];          // [FF][D] K-major
__device__ float g_w2T[D_ * FF_];          // [D][FF] K-major

// ---------------- helpers ----------------
__device__ __forceinline__ uint32_t smem_u32(const void* p) {
    uint32_t a;
    asm("{ .reg .u64 t; cvta.to.shared.u64 t, %1; cvt.u32.u64 %0, t; }" : "=r"(a) : "l"(p));
    return a;
}
__device__ __forceinline__ float rtf32(float x) {
    uint32_t u;
    asm("cvt.rna.tf32.f32 %0, %1;" : "=r"(u) : "f"(x));
    return __uint_as_float(u);
}
__device__ __forceinline__ void mma_tf32(float* c, const uint32_t* a, const uint32_t* b) {
    asm volatile(
        "mma.sync.aligned.m16n8k8.row.col.f32.tf32.tf32.f32 "
        "{%0,%1,%2,%3}, {%4,%5,%6,%7}, {%8,%9}, {%0,%1,%2,%3};"
        : "+f"(c[0]), "+f"(c[1]), "+f"(c[2]), "+f"(c[3])
        : "r"(a[0]), "r"(a[1]), "r"(a[2]), "r"(a[3]), "r"(b[0]), "r"(b[1]));
}
__device__ __forceinline__ void ldsm_x4(uint32_t* r, uint32_t addr) {
    asm volatile("ldmatrix.sync.aligned.m8n8.x4.shared.b16 {%0,%1,%2,%3}, [%4];"
        : "=r"(r[0]), "=r"(r[1]), "=r"(r[2]), "=r"(r[3]) : "r"(addr));
}

#define CP_ASYNC16(dst, src) \
    asm volatile("cp.async.cg.shared.global [%0], [%1], 16;" :: "r"(dst), "l"(src))
#define CP_COMMIT() asm volatile("cp.async.commit_group;" ::: "memory")
#define CP_WAIT(n)  asm volatile("cp.async.wait_group %0;" :: "n"(n) : "memory")

// ---------------- LayerNorm (+pos), output rounded to tf32 ----------------
__global__ void ln_kernel(const float* __restrict__ x,
                          const float* __restrict__ gamma,
                          const float* __restrict__ beta,
                          const float* __restrict__ pos,
                          float* __restrict__ out) {
    int row = blockIdx.x;
    int l = row & (L_ - 1);
    const float* xr = x + (size_t)row * D_;
    int t = threadIdx.x;
    float4 v = *(const float4*)(xr + t * 4);

    float s = v.x + v.y + v.z + v.w;
    float sq = v.x * v.x + v.y * v.y + v.z * v.z + v.w * v.w;
    #pragma unroll
    for (int o = 16; o > 0; o >>= 1) {
        s  += __shfl_down_sync(0xffffffffu, s,  o);
        sq += __shfl_down_sync(0xffffffffu, sq, o);
    }
    __shared__ float ss[8], sqs[8], stats[2];
    int wid = t >> 5, lane = t & 31;
    if (lane == 0) { ss[wid] = s; sqs[wid] = sq; }
    __syncthreads();
    if (t == 0) {
        float S = 0.f, SQ = 0.f;
        #pragma unroll
        for (int i = 0; i < 8; i++) { S += ss[i]; SQ += sqs[i]; }
        float mu = S / (float)D_;
        float var = SQ / (float)D_ - mu * mu;
        stats[0] = mu;
        stats[1] = rsqrtf(var + EPS_);
    }
    __syncthreads();
    float mu = stats[0], rs = stats[1];

    float4 g4 = *(const float4*)(gamma + t * 4);
    float4 b4 = *(const float4*)(beta + t * 4);
    float4 r;
    r.x = (v.x - mu) * rs * g4.x + b4.x;
    r.y = (v.y - mu) * rs * g4.y + b4.y;
    r.z = (v.z - mu) * rs * g4.z + b4.z;
    r.w = (v.w - mu) * rs * g4.w + b4.w;
    if (pos) {
        float4 p4 = *(const float4*)(pos + (size_t)l * D_ + t * 4);
        r.x += p4.x; r.y += p4.y; r.z += p4.z; r.w += p4.w;
    }
    r.x = rtf32(r.x); r.y = rtf32(r.y); r.z = rtf32(r.z); r.w = rtf32(r.w);
    *(float4*)(out + (size_t)row * D_ + t * 4) = r;
}

// ---------------- weight transpose + tf32 round: WT[n][k] = rtf32(W[k][n]) ----------------
__global__ void transpose_tf32(const float* __restrict__ W, float* __restrict__ WT, int K, int N) {
    __shared__ float tile[32][33];
    int n0 = blockIdx.x * 32, k0 = blockIdx.y * 32;
    int tx = threadIdx.x, ty = threadIdx.y;
    #pragma unroll
    for (int i = 0; i < 4; i++)
        tile[ty + 8 * i][tx] = W[(size_t)(k0 + ty + 8 * i) * N + n0 + tx];
    __syncthreads();
    #pragma unroll
    for (int i = 0; i < 4; i++)
        WT[(size_t)(n0 + ty + 8 * i) * K + k0 + tx] = rtf32(tile[tx][ty + 8 * i]);
}

// ---------------- tf32 mma.sync GEMM: 128x256 tile, 3-stage pipeline ----------------
// C[M,N] = A[M,K] @ BT[N,K]^T, both K-major, tf32-prerounded.
// 512 threads, 16 warps (4m x 4n), warp tile 32x64.
// flags: bit0 = gelu, bit1 = round output to tf32
#define AST 36
#define STAGE_FLOATS ((128 + 256) * AST)          // 13824
#define GEMM_SMEM_FLOATS (3 * STAGE_FLOATS + 256)
#define GEMM_SMEM_BYTES  (GEMM_SMEM_FLOATS * 4)

__global__ __launch_bounds__(512, 1)
void gemm_mma(const float* __restrict__ A, const float* __restrict__ BT,
              const float* __restrict__ bias, const float* __restrict__ addsrc,
              float* __restrict__ C, int M, int N, int K, int flags) {
    extern __shared__ float sm[];
    float* bias_s = sm + 3 * STAGE_FLOATS;

    int t = threadIdx.x;
    int wid = t >> 5, lane = t & 31;
    int wm = wid & 3, wn = wid >> 2;
    int gid = lane >> 2, tig = lane & 3;
    int n0 = blockIdx.x * 256, m0 = blockIdx.y * 128;

    uint32_t sA[3], sB[3];
    #pragma unroll
    for (int i = 0; i < 3; i++) {
        sA[i] = smem_u32(sm + i * STAGE_FLOATS);
        sB[i] = smem_u32(sm + i * STAGE_FLOATS + 128 * AST);
    }

    if (t < 64) {
        float4 bv = bias ? *(const float4*)(bias + n0 + t * 4) : make_float4(0.f, 0.f, 0.f, 0.f);
        *(float4*)(bias_s + t * 4) = bv;
    }

    // ldmatrix per-lane byte offsets
    int rsel = lane & 7;
    int t01  = (lane >> 3) & 1;
    int t23  = (lane >> 4) & 1;
    uint32_t aoff[2], boff[4];
    #pragma unroll
    for (int mf = 0; mf < 2; mf++)
        aoff[mf] = (uint32_t)(((wm * 32 + mf * 16 + t01 * 8 + rsel) * AST + t23 * 4) * 4);
    #pragma unroll
    for (int nf2 = 0; nf2 < 4; nf2++)
        boff[nf2] = (uint32_t)(((wn * 64 + nf2 * 16 + t23 * 8 + rsel) * AST + t01 * 4) * 4);

    // loader: A tile 128x32 (1024 f4 chunks, 2/thread), B tile 256x32 (2048 f4, 4/thread)
    #define LOAD_TILE(buf, kk0) do { \
        _Pragma("unroll") \
        for (int j = 0; j < 2; j++) { \
            int id = t + j * 512; \
            int row = id >> 3, c4 = id & 7; \
            CP_ASYNC16(sA[buf] + (uint32_t)(row * AST + c4 * 4) * 4u, \
                       A + (size_t)(m0 + row) * K + (kk0) + c4 * 4); \
        } \
        _Pragma("unroll") \
        for (int j = 0; j < 4; j++) { \
            int id = t + j * 512; \
            int row = id >> 3, c4 = id & 7; \
            CP_ASYNC16(sB[buf] + (uint32_t)(row * AST + c4 * 4) * 4u, \
                       BT + (size_t)(n0 + row) * K + (kk0) + c4 * 4); \
        } \
        CP_COMMIT(); \
    } while (0)

    float acc[2][8][4];
    #pragma unroll
    for (int i = 0; i < 2; i++)
        #pragma unroll
        for (int j = 0; j < 8; j++)
            #pragma unroll
            for (int c = 0; c < 4; c++) acc[i][j][c] = 0.f;

    const int NS = K >> 5;
    LOAD_TILE(0, 0);
    LOAD_TILE(1, 32);

    int buf = 0;
    for (int s = 0; s < NS; s++) {
        if (s < NS - 1) { CP_WAIT(1); } else { CP_WAIT(0); }
        __syncthreads();
        if (s + 2 < NS) {
            int nb = (buf + 2 >= 3) ? buf - 1 : buf + 2;
            LOAD_TILE(nb, (s + 2) << 5);
        }

        #pragma unroll
        for (int kk = 0; kk < 4; kk++) {
            uint32_t kadd = (uint32_t)(kk * 32);
            uint32_t af[2][4];
            ldsm_x4(af[0], sA[buf] + aoff[0] + kadd);
            ldsm_x4(af[1], sA[buf] + aoff[1] + kadd);
            uint32_t bf[16];
            #pragma unroll
            for (int nf2 = 0; nf2 < 4; nf2++)
                ldsm_x4(bf + nf2 * 4, sB[buf] + boff[nf2] + kadd);
            #pragma unroll
            for (int mf = 0; mf < 2; mf++)
                #pragma unroll
                for (int nf = 0; nf < 8; nf++)
                    mma_tf32(acc[mf][nf], af[mf], bf + nf * 2);
        }
        buf = (buf + 1 >= 3) ? 0 : buf + 1;
    }

    bool do_gelu = (flags & 1), do_round = (flags & 2);
    int row_base = m0 + wm * 32 + gid;
    int colw = wn * 64;
    #pragma unroll
    for (int mf = 0; mf < 2; mf++) {
        #pragma unroll
        for (int rr = 0; rr < 2; rr++) {
            int grow = row_base + mf * 16 + rr * 8;
            size_t roff = (size_t)grow * N + n0 + colw;
            #pragma unroll
            for (int nf = 0; nf < 8; nf++) {
                int cl = colw + nf * 8 + tig * 2;
                float v0 = acc[mf][nf][rr * 2 + 0] + bias_s[cl];
                float v1 = acc[mf][nf][rr * 2 + 1] + bias_s[cl + 1];
                if (do_gelu) {
                    v0 = 0.5f * v0 * (1.f + erff(v0 * 0.70710678118654752f));
                    v1 = 0.5f * v1 * (1.f + erff(v1 * 0.70710678118654752f));
                }
                if (addsrc) {
                    float2 sv = *(const float2*)(addsrc + roff + nf * 8 + tig * 2);
                    v0 += sv.x; v1 += sv.y;
                }
                if (do_round) { v0 = rtf32(v0); v1 = rtf32(v1); }
                *(float2*)(C + roff + nf * 8 + tig * 2) = make_float2(v0, v1);
            }
        }
    }
    #undef LOAD_TILE
}

// ---------------- fused attention, tf32 mma (flash-style) ----------------
// reads fused qkv buffer [B*L][3072]: q at col h*64, k at 1024+h*64, v at 2048+h*64
#define QST 68
#define VST 72
#define ATT_SMEM ((3 * 64 * QST + 64 * VST) * 4)

__global__ __launch_bounds__(128)
void attn_mma(const float* __restrict__ qkv, float* __restrict__ o) {
    extern __shared__ float sm[];
    float* Qs = sm;                    // [64][QST]  (q-row, d), pre-scaled
    float* Ks = sm + 64 * QST;         // [64][QST]  (kidx, d)
    float* Ps = sm + 2 * 64 * QST;     // [64][QST]  (q-row, kidx)
    float* Vs = sm + 3 * 64 * QST;     // [64][VST]  (kidx, d)

    int t = threadIdx.x;
    int w = t >> 5, lane = t & 31;
    int gid = lane >> 2, tig = lane & 3;
    int bh = blockIdx.y;
    int b = bh >> 4, h = bh & 15;
    int q0 = blockIdx.x * 64;
    int qrow = w * 16;
    size_t qbase = ((size_t)b * L_) * D3_ + (size_t)h * DH_;
    size_t obase = ((size_t)b * L_) * D_ + (size_t)h * DH_;
    const float scale = 0.125f;

    for (int i = t; i < 64 * 16; i += 128) {
        int r = i >> 4, c4 = i & 15;
        float4 vq = *(const float4*)(qkv + qbase + (size_t)(q0 + r) * D3_ + c4 * 4);
        vq.x *= scale; vq.y *= scale; vq.z *= scale; vq.w *= scale;
        *(float4*)&Qs[r * QST + c4 * 4] = vq;
    }

    float oacc[8][4];
    #pragma unroll
    for (int i = 0; i < 8; i++)
        #pragma unroll
        for (int j = 0; j < 4; j++) oacc[i][j] = 0.f;
    float m0 = -INFINITY, m1 = -INFINITY, l0 = 0.f, l1 = 0.f;

    for (int k0 = 0; k0 < L_; k0 += 64) {
        __syncthreads();
        for (int i = t; i < 64 * 16; i += 128) {
            int r = i >> 4, c4 = i & 15;
            float4 vk = *(const float4*)(qkv + qbase + 1024 + (size_t)(k0 + r) * D3_ + c4 * 4);
            *(float4*)&Ks[r * QST + c4 * 4] = vk;
            float4 vv = *(const float4*)(qkv + qbase + 2048 + (size_t)(k0 + r) * D3_ + c4 * 4);
            *(float4*)&Vs[r * VST + c4 * 4] = vv;
        }
        __syncthreads();

        float sacc[8][4];
        #pragma unroll
        for (int i = 0; i < 8; i++)
            #pragma unroll
            for (int j = 0; j < 4; j++) sacc[i][j] = 0.f;
        #pragma unroll
        for (int ks = 0; ks < 8; ks++) {
            int kb = ks * 8 + tig;
            uint32_t af[4];
            af[0] = __float_as_uint(Qs[(qrow + gid) * QST + kb]);
            af[1] = __float_as_uint(Qs[(qrow + gid + 8) * QST + kb]);
            af[2] = __float_as_uint(Qs[(qrow + gid) * QST + kb + 4]);
            af[3] = __float_as_uint(Qs[(qrow + gid + 8) * QST + kb + 4]);
            #pragma unroll
            for (int nf = 0; nf < 8; nf++) {
                uint32_t bf[2];
                bf[0] = __float_as_uint(Ks[(nf * 8 + gid) * QST + kb]);
                bf[1] = __float_as_uint(Ks[(nf * 8 + gid) * QST + kb + 4]);
                mma_tf32(sacc[nf], af, bf);
            }
        }

        float mx0 = -INFINITY, mx1 = -INFINITY;
        #pragma unroll
        for (int nf = 0; nf < 8; nf++) {
            mx0 = fmaxf(mx0, fmaxf(sacc[nf][0], sacc[nf][1]));
            mx1 = fmaxf(mx1, fmaxf(sacc[nf][2], sacc[nf][3]));
        }
        mx0 = fmaxf(mx0, __shfl_xor_sync(0xffffffffu, mx0, 1));
        mx0 = fmaxf(mx0, __shfl_xor_sync(0xffffffffu, mx0, 2));
        mx1 = fmaxf(mx1, __shfl_xor_sync(0xffffffffu, mx1, 1));
        mx1 = fmaxf(mx1, __shfl_xor_sync(0xffffffffu, mx1, 2));
        float mn0 = fmaxf(m0, mx0), mn1 = fmaxf(m1, mx1);
        float al0 = __expf(m0 - mn0), al1 = __expf(m1 - mn1);
        m0 = mn0; m1 = mn1;

        float sum0 = 0.f, sum1 = 0.f;
        #pragma unroll
        for (int nf = 0; nf < 8; nf++) {
            float p00 = __expf(sacc[nf][0] - m0);
            float p01 = __expf(sacc[nf][1] - m0);
            float p10 = __expf(sacc[nf][2] - m1);
            float p11 = __expf(sacc[nf][3] - m1);
            sum0 += p00 + p01;
            sum1 += p10 + p11;
            *(float2*)&Ps[(qrow + gid) * QST + nf * 8 + tig * 2] =
                make_float2(rtf32(p00), rtf32(p01));
            *(float2*)&Ps[(qrow + gid + 8) * QST + nf * 8 + tig * 2] =
                make_float2(rtf32(p10), rtf32(p11));
        }
        sum0 += __shfl_xor_sync(0xffffffffu, sum0, 1);
        sum0 += __shfl_xor_sync(0xffffffffu, sum0, 2);
        sum1 += __shfl_xor_sync(0xffffffffu, sum1, 1);
        sum1 += __shfl_xor_sync(0xffffffffu, sum1, 2);
        l0 = l0 * al0 + sum0;
        l1 = l1 * al1 + sum1;

        #pragma unroll
        for (int nf = 0; nf < 8; nf++) {
            oacc[nf][0] *= al0; oacc[nf][1] *= al0;
            oacc[nf][2] *= al1; oacc[nf][3] *= al1;
        }
        __syncwarp();

        #pragma unroll
        for (int ks = 0; ks < 8; ks++) {
            int kb = ks * 8 + tig;
            uint32_t af[4];
            af[0] = __float_as_uint(Ps[(qrow + gid) * QST + kb]);
            af[1] = __float_as_uint(Ps[(qrow + gid + 8) * QST + kb]);
            af[2] = __float_as_uint(Ps[(qrow + gid) * QST + kb + 4]);
            af[3] = __float_as_uint(Ps[(qrow + gid + 8) * QST + kb + 4]);
            #pragma unroll
            for (int nf = 0; nf < 8; nf++) {
                uint32_t bf[2];
                bf[0] = __float_as_uint(Vs[kb * VST + nf * 8 + gid]);
                bf[1] = __float_as_uint(Vs[(kb + 4) * VST + nf * 8 + gid]);
                mma_tf32(oacc[nf], af, bf);
            }
        }
    }

    float inv0 = 1.f / l0, inv1 = 1.f / l1;
    size_t r0off = obase + (size_t)(q0 + qrow + gid) * D_;
    size_t r1off = obase + (size_t)(q0 + qrow + gid + 8) * D_;
    #pragma unroll
    for (int nf = 0; nf < 8; nf++) {
        int c = nf * 8 + tig * 2;
        *(float2*)(o + r0off + c) = make_float2(rtf32(oacc[nf][0] * inv0), rtf32(oacc[nf][1] * inv0));
        *(float2*)(o + r1off + c) = make_float2(rtf32(oacc[nf][2] * inv1), rtf32(oacc[nf][3] * inv1));
    }
}

// ---------------- launch ----------------
extern "C" void kernel_launch(void* const* d_in, const int* in_sizes, int n_in,
                              void* d_out, int out_size) {
    const float* x     = (const float*)d_in[0];
    const float* pos   = (const float*)d_in[1];
    const float* ln1_g = (const float*)d_in[2];
    const float* ln1_b = (const float*)d_in[3];
    const float* Wq    = (const float*)d_in[4];
    const float* Wk    = (const float*)d_in[5];
    const float* Wv    = (const float*)d_in[6];
    const float* Wo    = (const float*)d_in[7];
    const float* bo    = (const float*)d_in[8];
    const float* ln2_g = (const float*)d_in[9];
    const float* ln2_b = (const float*)d_in[10];
    const float* W1    = (const float*)d_in[11];
    const float* b1    = (const float*)d_in[12];
    const float* W2    = (const float*)d_in[13];
    const float* b2    = (const float*)d_in[14];
    float* out = (float*)d_out;

    float *h, *qkv, *ao, *x2, *ff;
    float *wqkvT, *woT, *w1T, *w2T;
    cudaGetSymbolAddress((void**)&h,   g_h);
    cudaGetSymbolAddress((void**)&qkv, g_qkv);
    cudaGetSymbolAddress((void**)&ao,  g_ao);
    cudaGetSymbolAddress((void**)&x2,  g_x2);
    cudaGetSymbolAddress((void**)&ff,  g_ff);
    cudaGetSymbolAddress((void**)&wqkvT, g_wqkvT);
    cudaGetSymbolAddress((void**)&woT, g_woT);
    cudaGetSymbolAddress((void**)&w1T, g_w1T);
    cudaGetSymbolAddress((void**)&w2T, g_w2T);

    cudaFuncSetAttribute(gemm_mma, cudaFuncAttributeMaxDynamicSharedMemorySize, GEMM_SMEM_BYTES);
    cudaFuncSetAttribute(attn_mma, cudaFuncAttributeMaxDynamicSharedMemorySize, ATT_SMEM);

    const int ROWS = B_ * L_;   // 4096
    dim3 tb(32, 8);

    transpose_tf32<<<dim3(D_ / 32, D_ / 32), tb>>>(Wq, wqkvT,               D_, D_);
    transpose_tf32<<<dim3(D_ / 32, D_ / 32), tb>>>(Wk, wqkvT + D_ * D_,     D_, D_);
    transpose_tf32<<<dim3(D_ / 32, D_ / 32), tb>>>(Wv, wqkvT + 2 * D_ * D_, D_, D_);
    transpose_tf32<<<dim3(D_ / 32, D_ / 32), tb>>>(Wo, woT, D_, D_);
    transpose_tf32<<<dim3(FF_ / 32, D_ / 32), tb>>>(W1, w1T, D_, FF_);
    transpose_tf32<<<dim3(D_ / 32, FF_ / 32), tb>>>(W2, w2T, FF_, D_);

    // 1) h = round_tf32(LN1(x) + pos)
    ln_kernel<<<ROWS, 256>>>(x, ln1_g, ln1_b, pos, h);

    // 2) fused qkv = h @ [Wq|Wk|Wv]  (tf32-rounded outputs)
    {
        dim3 grid(D3_ / 256, ROWS / 128);
        gemm_mma<<<grid, 512, GEMM_SMEM_BYTES>>>(h, wqkvT, nullptr, nullptr, qkv, ROWS, D3_, D_, 2);
    }

    // 3) attention (tf32 mma flash)
    {
        dim3 grid(L_ / 64, B_ * H_);
        attn_mma<<<grid, 128, ATT_SMEM>>>(qkv, ao);
    }

    // 4) x2 = x + ao @ Wo + bo (exact fp32 residual)
    {
        dim3 grid(D_ / 256, ROWS / 128);
        gemm_mma<<<grid, 512, GEMM_SMEM_BYTES>>>(ao, woT, bo, x, x2, ROWS, D_, D_, 0);
    }

    // 5) h = round_tf32(LN2(x2))
    ln_kernel<<<ROWS, 256>>>(x2, ln2_g, ln2_b, nullptr, h);

    // 6) ff = round_tf32(gelu(h @ W1 + b1))
    {
        dim3 grid(FF_ / 256, ROWS / 128);
        gemm_mma<<<grid, 512, GEMM_SMEM_BYTES>>>(h, w1T, b1, nullptr, ff, ROWS, FF_, D_, 3);
    }

    // 7) out = x2 + ff @ W2 + b2
    {
        dim3 grid(D_ / 256, ROWS / 128);
        gemm_mma<<<grid, 512, GEMM_SMEM_BYTES>>>(ff, w2T, b2, x2, out, ROWS, D_, FF_, 0);
    }
}

// round 8
// speedup vs baseline: 5.7522x; 1.7689x over previous
#include <cuda_runtime.h>
#include <cuda_fp16.h>
#include <math.h>
#include <stdint.h>

#define B_ 2
#define L_ 2048
#define D_ 1024
#define H_ 16
#define DH_ 64
#define FF_ 4096
#define EPS_ 1e-5f
#define D3_ 3072

// ---------------- scratch (device globals) ----------------
__device__ __half g_h[B_ * L_ * D_];
__device__ __half g_qkv[B_ * L_ * D3_];
__device__ __half g_ao[B_ * L_ * D_];
__device__ float  g_x2[B_ * L_ * D_];
__device__ __half g_ff[B_ * L_ * FF_];
__device__ __half g_wqkvT[D3_ * D_];   // [3072][1024] K-major
__device__ __half g_woT[D_ * D_];
__device__ __half g_w1T[FF_ * D_];     // [FF][D]
__device__ __half g_w2T[D_ * FF_];     // [D][FF]

// ---------------- helpers ----------------
__device__ __forceinline__ uint32_t smem_u32(const void* p) {
    uint32_t a;
    asm("{ .reg .u64 t; cvta.to.shared.u64 t, %1; cvt.u32.u64 %0, t; }" : "=r"(a) : "l"(p));
    return a;
}
__device__ __forceinline__ void mma_f16(float* c, const uint32_t* a, uint32_t b0, uint32_t b1) {
    asm volatile(
        "mma.sync.aligned.m16n8k16.row.col.f32.f16.f16.f32 "
        "{%0,%1,%2,%3}, {%4,%5,%6,%7}, {%8,%9}, {%0,%1,%2,%3};"
        : "+f"(c[0]), "+f"(c[1]), "+f"(c[2]), "+f"(c[3])
        : "r"(a[0]), "r"(a[1]), "r"(a[2]), "r"(a[3]), "r"(b0), "r"(b1));
}
__device__ __forceinline__ void ldsm_x4(uint32_t* r, uint32_t addr) {
    asm volatile("ldmatrix.sync.aligned.m8n8.x4.shared.b16 {%0,%1,%2,%3}, [%4];"
        : "=r"(r[0]), "=r"(r[1]), "=r"(r[2]), "=r"(r[3]) : "r"(addr));
}
__device__ __forceinline__ void ldsm_x4_t(uint32_t* r, uint32_t addr) {
    asm volatile("ldmatrix.sync.aligned.m8n8.x4.trans.shared.b16 {%0,%1,%2,%3}, [%4];"
        : "=r"(r[0]), "=r"(r[1]), "=r"(r[2]), "=r"(r[3]) : "r"(addr));
}

#define CP_ASYNC16(dst, src) \
    asm volatile("cp.async.cg.shared.global [%0], [%1], 16;" :: "r"(dst), "l"(src))
#define CP_COMMIT() asm volatile("cp.async.commit_group;" ::: "memory")
#define CP_WAIT(n)  asm volatile("cp.async.wait_group %0;" :: "n"(n) : "memory")

// ---------------- LayerNorm (+pos), output fp16 ----------------
__global__ void ln_kernel(const float* __restrict__ x,
                          const float* __restrict__ gamma,
                          const float* __restrict__ beta,
                          const float* __restrict__ pos,
                          __half* __restrict__ out) {
    int row = blockIdx.x;
    int l = row & (L_ - 1);
    const float* xr = x + (size_t)row * D_;
    int t = threadIdx.x;
    float4 v = *(const float4*)(xr + t * 4);

    float s = v.x + v.y + v.z + v.w;
    float sq = v.x * v.x + v.y * v.y + v.z * v.z + v.w * v.w;
    #pragma unroll
    for (int o = 16; o > 0; o >>= 1) {
        s  += __shfl_down_sync(0xffffffffu, s,  o);
        sq += __shfl_down_sync(0xffffffffu, sq, o);
    }
    __shared__ float ss[8], sqs[8], stats[2];
    int wid = t >> 5, lane = t & 31;
    if (lane == 0) { ss[wid] = s; sqs[wid] = sq; }
    __syncthreads();
    if (t == 0) {
        float S = 0.f, SQ = 0.f;
        #pragma unroll
        for (int i = 0; i < 8; i++) { S += ss[i]; SQ += sqs[i]; }
        float mu = S / (float)D_;
        float var = SQ / (float)D_ - mu * mu;
        stats[0] = mu;
        stats[1] = rsqrtf(var + EPS_);
    }
    __syncthreads();
    float mu = stats[0], rs = stats[1];

    float4 g4 = *(const float4*)(gamma + t * 4);
    float4 b4 = *(const float4*)(beta + t * 4);
    float4 r;
    r.x = (v.x - mu) * rs * g4.x + b4.x;
    r.y = (v.y - mu) * rs * g4.y + b4.y;
    r.z = (v.z - mu) * rs * g4.z + b4.z;
    r.w = (v.w - mu) * rs * g4.w + b4.w;
    if (pos) {
        float4 p4 = *(const float4*)(pos + (size_t)l * D_ + t * 4);
        r.x += p4.x; r.y += p4.y; r.z += p4.z; r.w += p4.w;
    }
    __half2 h0 = __floats2half2_rn(r.x, r.y);
    __half2 h1 = __floats2half2_rn(r.z, r.w);
    uint2 pk = make_uint2(*(uint32_t*)&h0, *(uint32_t*)&h1);
    *(uint2*)(out + (size_t)row * D_ + t * 4) = pk;
}

// ---------------- weight transpose + fp16 round: WT[n][k] = h(W[k][n]) ----------------
__global__ void transpose_h(const float* __restrict__ W, __half* __restrict__ WT, int K, int N) {
    __shared__ float tile[32][33];
    int n0 = blockIdx.x * 32, k0 = blockIdx.y * 32;
    int tx = threadIdx.x, ty = threadIdx.y;
    #pragma unroll
    for (int i = 0; i < 4; i++)
        tile[ty + 8 * i][tx] = W[(size_t)(k0 + ty + 8 * i) * N + n0 + tx];
    __syncthreads();
    #pragma unroll
    for (int i = 0; i < 4; i++)
        WT[(size_t)(n0 + ty + 8 * i) * K + k0 + tx] = __float2half_rn(tile[tx][ty + 8 * i]);
}

// ---------------- fp16 mma GEMM: 128x256 tile, BK=64, 3-stage ----------------
// C[M,N] = A[M,K] @ BT[N,K]^T, halves, fp32 accum.
// flags: bit0 = gelu, bit2 = output half (else float)
#define AST 72
#define STAGE_HALVES ((128 + 256) * AST)          // 27648
#define GEMM_SMEM_BYTES (3 * STAGE_HALVES * 2 + 256 * 4)

__global__ __launch_bounds__(512, 1)
void gemm_mma(const __half* __restrict__ A, const __half* __restrict__ BT,
              const float* __restrict__ bias, const float* __restrict__ addsrc,
              void* __restrict__ Cout, int M, int N, int K, int flags) {
    extern __shared__ __half smh[];
    float* bias_s = (float*)(smh + 3 * STAGE_HALVES);

    int t = threadIdx.x;
    int wid = t >> 5, lane = t & 31;
    int wm = wid & 3, wn = wid >> 2;
    int gid = lane >> 2, tig = lane & 3;
    int n0 = blockIdx.x * 256, m0 = blockIdx.y * 128;

    uint32_t sA[3], sB[3];
    #pragma unroll
    for (int i = 0; i < 3; i++) {
        sA[i] = smem_u32(smh + i * STAGE_HALVES);
        sB[i] = sA[i] + 128 * AST * 2;
    }

    if (t < 64) {
        float4 bv = bias ? *(const float4*)(bias + n0 + t * 4) : make_float4(0.f, 0.f, 0.f, 0.f);
        *(float4*)(bias_s + t * 4) = bv;
    }

    int rsel = lane & 7;
    int t01  = (lane >> 3) & 1;
    int t23  = (lane >> 4) & 1;
    uint32_t aoff[2], boff[4];
    #pragma unroll
    for (int mf = 0; mf < 2; mf++)
        aoff[mf] = (uint32_t)(((wm * 32 + mf * 16 + t01 * 8 + rsel) * AST + t23 * 8) * 2);
    #pragma unroll
    for (int nf2 = 0; nf2 < 4; nf2++)
        boff[nf2] = (uint32_t)(((wn * 64 + nf2 * 16 + t01 * 8 + rsel) * AST + t23 * 8) * 2);

    // loader: A 128x64h = 1024 chunks (2/thr), B 256x64h = 2048 chunks (4/thr); 16B chunks
    #define LOAD_TILE(buf, kk0) do { \
        _Pragma("unroll") \
        for (int j = 0; j < 2; j++) { \
            int id = t + j * 512; \
            int row = id >> 3, c4 = id & 7; \
            CP_ASYNC16(sA[buf] + (uint32_t)(row * AST + c4 * 8) * 2u, \
                       A + (size_t)(m0 + row) * K + (kk0) + c4 * 8); \
        } \
        _Pragma("unroll") \
        for (int j = 0; j < 4; j++) { \
            int id = t + j * 512; \
            int row = id >> 3, c4 = id & 7; \
            CP_ASYNC16(sB[buf] + (uint32_t)(row * AST + c4 * 8) * 2u, \
                       BT + (size_t)(n0 + row) * K + (kk0) + c4 * 8); \
        } \
        CP_COMMIT(); \
    } while (0)

    float acc[2][8][4];
    #pragma unroll
    for (int i = 0; i < 2; i++)
        #pragma unroll
        for (int j = 0; j < 8; j++)
            #pragma unroll
            for (int c = 0; c < 4; c++) acc[i][j][c] = 0.f;

    const int NS = K >> 6;
    LOAD_TILE(0, 0);
    LOAD_TILE(1, 64);

    int buf = 0;
    for (int s = 0; s < NS; s++) {
        if (s < NS - 1) { CP_WAIT(1); } else { CP_WAIT(0); }
        __syncthreads();
        if (s + 2 < NS) {
            int nb = (buf + 2 >= 3) ? buf - 1 : buf + 2;
            LOAD_TILE(nb, (s + 2) << 6);
        }

        #pragma unroll
        for (int kk = 0; kk < 4; kk++) {
            uint32_t kadd = (uint32_t)(kk * 32);   // 16 halves
            uint32_t af[2][4];
            ldsm_x4(af[0], sA[buf] + aoff[0] + kadd);
            ldsm_x4(af[1], sA[buf] + aoff[1] + kadd);
            uint32_t bf[4][4];
            #pragma unroll
            for (int nf2 = 0; nf2 < 4; nf2++)
                ldsm_x4(bf[nf2], sB[buf] + boff[nf2] + kadd);
            #pragma unroll
            for (int mf = 0; mf < 2; mf++)
                #pragma unroll
                for (int nf2 = 0; nf2 < 4; nf2++) {
                    mma_f16(acc[mf][nf2 * 2],     af[mf], bf[nf2][0], bf[nf2][2]);
                    mma_f16(acc[mf][nf2 * 2 + 1], af[mf], bf[nf2][1], bf[nf2][3]);
                }
        }
        buf = (buf + 1 >= 3) ? 0 : buf + 1;
    }

    bool do_gelu = (flags & 1), out_half = (flags & 4);
    float* Cf = (float*)Cout;
    __half* Ch = (__half*)Cout;
    int row_base = m0 + wm * 32 + gid;
    int colw = wn * 64;
    #pragma unroll
    for (int mf = 0; mf < 2; mf++) {
        #pragma unroll
        for (int rr = 0; rr < 2; rr++) {
            int grow = row_base + mf * 16 + rr * 8;
            size_t roff = (size_t)grow * N + n0 + colw;
            #pragma unroll
            for (int nf = 0; nf < 8; nf++) {
                int cl = colw + nf * 8 + tig * 2;
                float v0 = acc[mf][nf][rr * 2 + 0] + bias_s[cl];
                float v1 = acc[mf][nf][rr * 2 + 1] + bias_s[cl + 1];
                if (do_gelu) {
                    v0 = 0.5f * v0 * (1.f + erff(v0 * 0.70710678118654752f));
                    v1 = 0.5f * v1 * (1.f + erff(v1 * 0.70710678118654752f));
                }
                if (addsrc) {
                    float2 sv = *(const float2*)(addsrc + roff + nf * 8 + tig * 2);
                    v0 += sv.x; v1 += sv.y;
                }
                if (out_half) {
                    __half2 hv = __floats2half2_rn(v0, v1);
                    *(__half2*)(Ch + roff + nf * 8 + tig * 2) = hv;
                } else {
                    *(float2*)(Cf + roff + nf * 8 + tig * 2) = make_float2(v0, v1);
                }
            }
        }
    }
    #undef LOAD_TILE
}

// ---------------- fused attention, fp16 mma (flash-style) ----------------
#define ST_ 72
#define ATT_SMEM (4 * 64 * ST_ * 2)

__global__ __launch_bounds__(128)
void attn_mma(const __half* __restrict__ qkv, __half* __restrict__ o) {
    extern __shared__ __half smh[];
    __half* Qs = smh;                  // [64][ST_] (q-row, d), pre-scaled
    __half* Ks = smh + 64 * ST_;       // [64][ST_] (kidx, d)
    __half* Ps = smh + 2 * 64 * ST_;   // [64][ST_] (q-row, kidx)
    __half* Vs = smh + 3 * 64 * ST_;   // [64][ST_] (kidx, d)
    uint32_t uQ = smem_u32(Qs), uK = smem_u32(Ks), uP = smem_u32(Ps), uV = smem_u32(Vs);

    int t = threadIdx.x;
    int w = t >> 5, lane = t & 31;
    int gid = lane >> 2, tig = lane & 3;
    int bh = blockIdx.y;
    int b = bh >> 4, h = bh & 15;
    int q0 = blockIdx.x * 64;
    int qrow = w * 16;
    size_t qbase = ((size_t)b * L_) * D3_ + (size_t)h * DH_;
    size_t obase = ((size_t)b * L_) * D_ + (size_t)h * DH_;

    int rsel = lane & 7;
    int t01  = (lane >> 3) & 1;
    int t23  = (lane >> 4) & 1;
    uint32_t qaoff = (uint32_t)(((qrow + t01 * 8 + rsel) * ST_ + t23 * 8) * 2);
    uint32_t kboff[4], vboff[4];
    #pragma unroll
    for (int nf2 = 0; nf2 < 4; nf2++) {
        kboff[nf2] = (uint32_t)(((nf2 * 16 + t01 * 8 + rsel) * ST_ + t23 * 8) * 2);
        vboff[nf2] = (uint32_t)(((t01 * 8 + rsel) * ST_ + nf2 * 16 + t23 * 8) * 2);
    }

    // load + scale Q (scale=0.125 is exact in fp16)
    const __half2 sc2 = __floats2half2_rn(0.125f, 0.125f);
    #pragma unroll
    for (int j = 0; j < 4; j++) {
        int i = t + j * 128;
        int r = i >> 3, c4 = i & 7;
        uint4 v = *(const uint4*)(qkv + qbase + (size_t)(q0 + r) * D3_ + c4 * 8);
        __half2* hp = (__half2*)&v;
        hp[0] = __hmul2(hp[0], sc2); hp[1] = __hmul2(hp[1], sc2);
        hp[2] = __hmul2(hp[2], sc2); hp[3] = __hmul2(hp[3], sc2);
        *(uint4*)(Qs + r * ST_ + c4 * 8) = v;
    }

    float oacc[8][4];
    #pragma unroll
    for (int i = 0; i < 8; i++)
        #pragma unroll
        for (int j = 0; j < 4; j++) oacc[i][j] = 0.f;
    float m0 = -INFINITY, m1 = -INFINITY, l0 = 0.f, l1 = 0.f;

    for (int k0 = 0; k0 < L_; k0 += 64) {
        __syncthreads();
        #pragma unroll
        for (int j = 0; j < 4; j++) {
            int i = t + j * 128;
            int r = i >> 3, c4 = i & 7;
            *(uint4*)(Ks + r * ST_ + c4 * 8) =
                *(const uint4*)(qkv + qbase + 1024 + (size_t)(k0 + r) * D3_ + c4 * 8);
            *(uint4*)(Vs + r * ST_ + c4 * 8) =
                *(const uint4*)(qkv + qbase + 2048 + (size_t)(k0 + r) * D3_ + c4 * 8);
        }
        __syncthreads();

        // S = Q @ K^T : m16 x n64, k=64
        float sacc[8][4];
        #pragma unroll
        for (int i = 0; i < 8; i++)
            #pragma unroll
            for (int j = 0; j < 4; j++) sacc[i][j] = 0.f;
        #pragma unroll
        for (int kk = 0; kk < 4; kk++) {
            uint32_t kadd = (uint32_t)(kk * 32);
            uint32_t af[4];
            ldsm_x4(af, uQ + qaoff + kadd);
            #pragma unroll
            for (int nf2 = 0; nf2 < 4; nf2++) {
                uint32_t bf[4];
                ldsm_x4(bf, uK + kboff[nf2] + kadd);
                mma_f16(sacc[nf2 * 2],     af, bf[0], bf[2]);
                mma_f16(sacc[nf2 * 2 + 1], af, bf[1], bf[3]);
            }
        }

        // online softmax
        float mx0 = -INFINITY, mx1 = -INFINITY;
        #pragma unroll
        for (int nf = 0; nf < 8; nf++) {
            mx0 = fmaxf(mx0, fmaxf(sacc[nf][0], sacc[nf][1]));
            mx1 = fmaxf(mx1, fmaxf(sacc[nf][2], sacc[nf][3]));
        }
        mx0 = fmaxf(mx0, __shfl_xor_sync(0xffffffffu, mx0, 1));
        mx0 = fmaxf(mx0, __shfl_xor_sync(0xffffffffu, mx0, 2));
        mx1 = fmaxf(mx1, __shfl_xor_sync(0xffffffffu, mx1, 1));
        mx1 = fmaxf(mx1, __shfl_xor_sync(0xffffffffu, mx1, 2));
        float mn0 = fmaxf(m0, mx0), mn1 = fmaxf(m1, mx1);
        float al0 = __expf(m0 - mn0), al1 = __expf(m1 - mn1);
        m0 = mn0; m1 = mn1;

        float sum0 = 0.f, sum1 = 0.f;
        #pragma unroll
        for (int nf = 0; nf < 8; nf++) {
            float p00 = __expf(sacc[nf][0] - m0);
            float p01 = __expf(sacc[nf][1] - m0);
            float p10 = __expf(sacc[nf][2] - m1);
            float p11 = __expf(sacc[nf][3] - m1);
            sum0 += p00 + p01;
            sum1 += p10 + p11;
            *(__half2*)(Ps + (qrow + gid) * ST_ + nf * 8 + tig * 2) = __floats2half2_rn(p00, p01);
            *(__half2*)(Ps + (qrow + gid + 8) * ST_ + nf * 8 + tig * 2) = __floats2half2_rn(p10, p11);
        }
        sum0 += __shfl_xor_sync(0xffffffffu, sum0, 1);
        sum0 += __shfl_xor_sync(0xffffffffu, sum0, 2);
        sum1 += __shfl_xor_sync(0xffffffffu, sum1, 1);
        sum1 += __shfl_xor_sync(0xffffffffu, sum1, 2);
        l0 = l0 * al0 + sum0;
        l1 = l1 * al1 + sum1;

        #pragma unroll
        for (int nf = 0; nf < 8; nf++) {
            oacc[nf][0] *= al0; oacc[nf][1] *= al0;
            oacc[nf][2] *= al1; oacc[nf][3] *= al1;
        }
        __syncwarp();

        // O += P @ V : A = P (rows q, k=kidx), B = V via .trans
        #pragma unroll
        for (int kk = 0; kk < 4; kk++) {
            uint32_t af[4];
            ldsm_x4(af, uP + qaoff + (uint32_t)(kk * 32));
            uint32_t kaddv = (uint32_t)(kk * 16 * ST_ * 2);
            #pragma unroll
            for (int nf2 = 0; nf2 < 4; nf2++) {
                uint32_t bf[4];
                ldsm_x4_t(bf, uV + vboff[nf2] + kaddv);
                mma_f16(oacc[nf2 * 2],     af, bf[0], bf[1]);
                mma_f16(oacc[nf2 * 2 + 1], af, bf[2], bf[3]);
            }
        }
    }

    float inv0 = 1.f / l0, inv1 = 1.f / l1;
    size_t r0off = obase + (size_t)(q0 + qrow + gid) * D_;
    size_t r1off = obase + (size_t)(q0 + qrow + gid + 8) * D_;
    #pragma unroll
    for (int nf = 0; nf < 8; nf++) {
        int c = nf * 8 + tig * 2;
        *(__half2*)(o + r0off + c) = __floats2half2_rn(oacc[nf][0] * inv0, oacc[nf][1] * inv0);
        *(__half2*)(o + r1off + c) = __floats2half2_rn(oacc[nf][2] * inv1, oacc[nf][3] * inv1);
    }
}

// ---------------- launch ----------------
extern "C" void kernel_launch(void* const* d_in, const int* in_sizes, int n_in,
                              void* d_out, int out_size) {
    const float* x     = (const float*)d_in[0];
    const float* pos   = (const float*)d_in[1];
    const float* ln1_g = (const float*)d_in[2];
    const float* ln1_b = (const float*)d_in[3];
    const float* Wq    = (const float*)d_in[4];
    const float* Wk    = (const float*)d_in[5];
    const float* Wv    = (const float*)d_in[6];
    const float* Wo    = (const float*)d_in[7];
    const float* bo    = (const float*)d_in[8];
    const float* ln2_g = (const float*)d_in[9];
    const float* ln2_b = (const float*)d_in[10];
    const float* W1    = (const float*)d_in[11];
    const float* b1    = (const float*)d_in[12];
    const float* W2    = (const float*)d_in[13];
    const float* b2    = (const float*)d_in[14];
    float* out = (float*)d_out;

    __half *h, *qkv, *ao, *ff, *wqkvT, *woT, *w1T, *w2T;
    float *x2;
    cudaGetSymbolAddress((void**)&h,   g_h);
    cudaGetSymbolAddress((void**)&qkv, g_qkv);
    cudaGetSymbolAddress((void**)&ao,  g_ao);
    cudaGetSymbolAddress((void**)&x2,  g_x2);
    cudaGetSymbolAddress((void**)&ff,  g_ff);
    cudaGetSymbolAddress((void**)&wqkvT, g_wqkvT);
    cudaGetSymbolAddress((void**)&woT, g_woT);
    cudaGetSymbolAddress((void**)&w1T, g_w1T);
    cudaGetSymbolAddress((void**)&w2T, g_w2T);

    cudaFuncSetAttribute(gemm_mma, cudaFuncAttributeMaxDynamicSharedMemorySize, GEMM_SMEM_BYTES);
    cudaFuncSetAttribute(attn_mma, cudaFuncAttributeMaxDynamicSharedMemorySize, ATT_SMEM);

    const int ROWS = B_ * L_;   // 4096
    dim3 tb(32, 8);

    transpose_h<<<dim3(D_ / 32, D_ / 32), tb>>>(Wq, wqkvT,               D_, D_);
    transpose_h<<<dim3(D_ / 32, D_ / 32), tb>>>(Wk, wqkvT + D_ * D_,     D_, D_);
    transpose_h<<<dim3(D_ / 32, D_ / 32), tb>>>(Wv, wqkvT + 2 * D_ * D_, D_, D_);
    transpose_h<<<dim3(D_ / 32, D_ / 32), tb>>>(Wo, woT, D_, D_);
    transpose_h<<<dim3(FF_ / 32, D_ / 32), tb>>>(W1, w1T, D_, FF_);
    transpose_h<<<dim3(D_ / 32, FF_ / 32), tb>>>(W2, w2T, FF_, D_);

    // 1) h = fp16(LN1(x) + pos)
    ln_kernel<<<ROWS, 256>>>(x, ln1_g, ln1_b, pos, h);

    // 2) fused qkv = h @ [Wq|Wk|Wv]  (half out)
    {
        dim3 grid(D3_ / 256, ROWS / 128);
        gemm_mma<<<grid, 512, GEMM_SMEM_BYTES>>>(h, wqkvT, nullptr, nullptr, qkv, ROWS, D3_, D_, 4);
    }

    // 3) attention (fp16 mma flash) -> ao (half)
    {
        dim3 grid(L_ / 64, B_ * H_);
        attn_mma<<<grid, 128, ATT_SMEM>>>(qkv, ao);
    }

    // 4) x2 = x + ao @ Wo + bo  (float out, exact residual)
    {
        dim3 grid(D_ / 256, ROWS / 128);
        gemm_mma<<<grid, 512, GEMM_SMEM_BYTES>>>(ao, woT, bo, x, x2, ROWS, D_, D_, 0);
    }

    // 5) h = fp16(LN2(x2))
    ln_kernel<<<ROWS, 256>>>(x2, ln2_g, ln2_b, nullptr, h);

    // 6) ff = fp16(gelu(h @ W1 + b1))
    {
        dim3 grid(FF_ / 256, ROWS / 128);
        gemm_mma<<<grid, 512, GEMM_SMEM_BYTES>>>(h, w1T, b1, nullptr, ff, ROWS, FF_, D_, 5);
    }

    // 7) out = x2 + ff @ W2 + b2  (float out)
    {
        dim3 grid(D_ / 256, ROWS / 128);
        gemm_mma<<<grid, 512, GEMM_SMEM_BYTES>>>(ff, w2T, b2, x2, out, ROWS, D_, FF_, 0);
    }
}